// round 12
// baseline (speedup 1.0000x reference)
#include <cuda_runtime.h>
#include <cstdint>

// Problem constants
#define NB    8
#define NTOK  16384
#define NC    256
#define NWIN  2048    // B * (16x16 windows)
#define QKVW  768     // q(256) | k(256) | v(256)

// g_qkv channel dims stored PERMUTED within 8-groups:
// position p holds channel c(p) = (p&1)*4 + (p>>1)   (order 0,4,1,5,2,6,3,7)
__device__ float g_qkv[(size_t)NWIN * 64 * QKVW];
__device__ float g_wqk[512 * 256];     // rounded + permuted cols (rows natural)
__device__ float g_wv[256 * 256];
__device__ float g_wproj[256 * 256];

// ---------------------------------------------------------------------------
__device__ __forceinline__ uint32_t f2tf(float f) {
    uint32_t u;
    asm("cvt.rna.tf32.f32 %0, %1;" : "=r"(u) : "f"(f));
    return u;
}
__device__ __forceinline__ float ftf(float f) {
    return __uint_as_float(f2tf(f));
}
__device__ __forceinline__ void mma_tf32(float c[4],
    uint32_t a0, uint32_t a1, uint32_t a2, uint32_t a3,
    uint32_t b0, uint32_t b1)
{
    asm volatile(
        "mma.sync.aligned.m16n8k8.row.col.f32.tf32.tf32.f32 "
        "{%0,%1,%2,%3},{%4,%5,%6,%7},{%8,%9},{%0,%1,%2,%3};"
        : "+f"(c[0]), "+f"(c[1]), "+f"(c[2]), "+f"(c[3])
        : "r"(a0), "r"(a1), "r"(a2), "r"(a3), "r"(b0), "r"(b1));
}
// FMA-pipe exponential (avoids the MUFU bottleneck).
// exp(x) = 2^(x*log2e); n extracted via 1.5*2^23 magic add; 2^r by deg-5 Taylor.
__device__ __forceinline__ float fast_exp(float x) {
    x = fminf(fmaxf(x, -80.f), 80.f);
    float t = x * 1.4426950408889634f;
    float z = t + 12582912.0f;              // round-to-nearest-int in mantissa
    int   i = __float_as_int(z);            // low bits hold n (two's complement)
    float n = z - 12582912.0f;
    float r = t - n;                         // r in [-0.5, 0.5]
    float p = 1.3333558146428443e-3f;
    p = fmaf(p, r, 9.6181291976956498e-3f);
    p = fmaf(p, r, 5.5504108664821580e-2f);
    p = fmaf(p, r, 2.4022650695910072e-1f);
    p = fmaf(p, r, 6.9314718055994531e-1f);
    p = fmaf(p, r, 1.0f);
    float s = __int_as_float((i + 127) << 23);   // 2^n
    return p * s;
}
#define CPA16(dst, src) \
    asm volatile("cp.async.cg.shared.global [%0],[%1],16;" :: "r"(dst), "l"(src))
#define CP_COMMIT() asm volatile("cp.async.commit_group;")
#define CP_WAIT0()  asm volatile("cp.async.wait_group 0;" ::: "memory")

// qkv GEMM tiles: BM=128, BN=64, BK=32, 256 threads (8 warps of 32x32)
#define TS      36
#define ATILE_F (128 * TS)
#define BTILE_F (64 * TS)
#define BUF2_F  (ATILE_F + BTILE_F)
#define SMEM_G2 (2 * BUF2_F * 4)      // 55296 B -> 4 CTAs/SM

// ---------------------------------------------------------------------------
// Weights: round to tf32 + permute 8-groups (rows natural)
// ---------------------------------------------------------------------------
__global__ __launch_bounds__(256) void cvt_weights(
    const float* __restrict__ wqk, const float* __restrict__ wv,
    const float* __restrict__ wproj)
{
    const int t = blockIdx.x * 256 + threadIdx.x;
    const int off = t * 8;
    const float* s; float* d;
    if (off < 131072)      { s = wqk + off;           d = g_wqk + off; }
    else if (off < 196608) { s = wv + off - 131072;   d = g_wv + off - 131072; }
    else                   { s = wproj + off - 196608; d = g_wproj + off - 196608; }
    float4 v0 = ((const float4*)s)[0], v1 = ((const float4*)s)[1];
    ((float4*)d)[0] = make_float4(ftf(v0.x), ftf(v1.x), ftf(v0.y), ftf(v1.y));
    ((float4*)d)[1] = make_float4(ftf(v0.z), ftf(v1.z), ftf(v0.w), ftf(v1.w));
}

// ---------------------------------------------------------------------------
// Kernel A: Q|K|V GEMM (R7 config: 128x64 tile, 4 CTAs/SM).
// GRID SWAPPED: cb = blockIdx.x (fast) -> 12 CTAs sharing an A tile co-run.
// ---------------------------------------------------------------------------
__global__ __launch_bounds__(256, 4) void qkv_mma(
    const float* __restrict__ x, const float* __restrict__ query)
{
    extern __shared__ float sm[];
    const int tid = threadIdx.x;
    const int cb  = blockIdx.x;     // 0..11
    const int p   = blockIdx.y;     // 0..1023

    const float* in = (cb < 8) ? query : x;
    const float* Wt = (cb < 8) ? (g_wqk + (long)cb * 64 * 256)
                               : (g_wv  + (long)(cb - 8) * 64 * 256);
    const int dstcol = (cb < 8) ? cb * 64 : 512 + (cb - 8) * 64;

    const int ldrA = tid >> 1, ldcA = (tid & 1) << 4;
    const int ldrB = tid >> 2, ldcB = (tid & 3) << 3;
    int win = p * 2 + (ldrA >> 6);
    int s   = ldrA & 63;
    int b   = win >> 8, g = win & 255;
    int n   = ((g >> 4) * 8 + (s >> 3)) * 128 + (g & 15) * 8 + (s & 7);
    const float* a_src0 = in + ((long)b * NTOK + n) * 256 + ldcA;
    const float* b_src0 = Wt + (long)ldrB * 256 + ldcB;

    uint32_t smem_base = (uint32_t)__cvta_generic_to_shared(sm);
    uint32_t a_dst0 = smem_base + (uint32_t)(ldrA * TS + ldcA) * 4;
    uint32_t b_dst0 = smem_base + (uint32_t)(ATILE_F + ldrB * TS + ldcB) * 4;

    const int lane = tid & 31, w = tid >> 5;
    const int wm = (w >> 1) * 32;
    const int wn = (w & 1) * 32;
    const int gq = lane >> 2, tg = lane & 3;

    float acc[2][4][4];
    #pragma unroll
    for (int mt = 0; mt < 2; mt++)
        #pragma unroll
        for (int nt = 0; nt < 4; nt++)
            #pragma unroll
            for (int q = 0; q < 4; q++) acc[mt][nt][q] = 0.f;

    {
        #pragma unroll
        for (int i = 0; i < 4; i++) CPA16(a_dst0 + i * 16, a_src0 + i * 4);
        #pragma unroll
        for (int i = 0; i < 2; i++) CPA16(b_dst0 + i * 16, b_src0 + i * 4);
        CP_COMMIT();
    }

    for (int kb = 0; kb < 8; ++kb) {
        CP_WAIT0();
        __syncthreads();
        if (kb < 7) {
            uint32_t off = (uint32_t)(((kb + 1) & 1) * BUF2_F * 4);
            const float* as = a_src0 + (kb + 1) * 32;
            const float* bs = b_src0 + (kb + 1) * 32;
            #pragma unroll
            for (int i = 0; i < 4; i++) CPA16(a_dst0 + off + i * 16, as + i * 4);
            #pragma unroll
            for (int i = 0; i < 2; i++) CPA16(b_dst0 + off + i * 16, bs + i * 4);
            CP_COMMIT();
        }
        const float* sA = sm + (kb & 1) * BUF2_F;
        const float* sB = sA + ATILE_F;

        #pragma unroll
        for (int ks = 0; ks < 4; ++ks) {
            const int k0n = ks * 8;
            const int k0p = ks * 8 + 2 * tg;
            uint32_t af[2][4];
            #pragma unroll
            for (int mt = 0; mt < 2; mt++) {
                const int r0 = wm + mt * 16;
                af[mt][0] = f2tf(sA[(r0 + gq)     * TS + k0n + tg]);
                af[mt][1] = f2tf(sA[(r0 + gq + 8) * TS + k0n + tg]);
                af[mt][2] = f2tf(sA[(r0 + gq)     * TS + k0n + tg + 4]);
                af[mt][3] = f2tf(sA[(r0 + gq + 8) * TS + k0n + tg + 4]);
            }
            #pragma unroll
            for (int nt = 0; nt < 4; nt++) {
                float2 bv = *(const float2*)&sB[(wn + nt * 8 + gq) * TS + k0p];
                uint32_t b0 = __float_as_uint(bv.x);
                uint32_t b1 = __float_as_uint(bv.y);
                mma_tf32(acc[0][nt], af[0][0], af[0][1], af[0][2], af[0][3], b0, b1);
                mma_tf32(acc[1][nt], af[1][0], af[1][1], af[1][2], af[1][3], b0, b1);
            }
        }
    }

    const long row0 = (long)p * 128;
    const int pb = (tg & 1) * 4 + (tg >> 1);
    #pragma unroll
    for (int mt = 0; mt < 2; mt++) {
        #pragma unroll
        for (int nt = 0; nt < 4; nt++) {
            const int gb = dstcol + wn + nt * 8;
            const long r1 = row0 + wm + mt * 16 + gq;
            g_qkv[r1 * QKVW + gb + pb]           = ftf(acc[mt][nt][0]);
            g_qkv[r1 * QKVW + gb + pb + 2]       = ftf(acc[mt][nt][1]);
            g_qkv[(r1 + 8) * QKVW + gb + pb]     = ftf(acc[mt][nt][2]);
            g_qkv[(r1 + 8) * QKVW + gb + pb + 2] = ftf(acc[mt][nt][3]);
        }
    }
}

// ---------------------------------------------------------------------------
// Kernel B: attention — R11 verbatim except __expf -> fast_exp (FMA pipe).
// ---------------------------------------------------------------------------
#define PL2 2116
#define RS  66
#define OFF_WPRE  (8 * PL2)
#define OFF_WPOST (OFF_WPRE + 64)
#define OFF_RSUM  (OFF_WPRE + 128)
#define SMEM_ATTN_BYTES ((OFF_RSUM + 256) * 4)

__global__ __launch_bounds__(256) void attn_kernel(
    const float* __restrict__ W_pre, const float* __restrict__ W_post)
{
    extern __shared__ float sm[];
    float* s_attn  = sm;
    float* s_wpre  = sm + OFF_WPRE;
    float* s_wpost = sm + OFF_WPOST;
    float* s_rsum  = sm + OFF_RSUM;

    const int tid  = threadIdx.x;
    const int lane = tid & 31;
    const int h    = tid >> 5;
    const int gq = lane >> 2, tg = lane & 3;
    const int h32 = h * 32;
    const int win = blockIdx.x >> 1;
    const int qb  = (blockIdx.x & 1) * 32;
    const long rowbase = (long)win * 64;
    const float* gq_base = g_qkv + rowbase * QKVW;

    if (tid < 64) { s_wpre[tid] = W_pre[tid]; s_wpost[tid] = W_post[tid]; }

    float acc[2][8][4];
    #pragma unroll
    for (int mt = 0; mt < 2; mt++)
        #pragma unroll
        for (int nt = 0; nt < 8; nt++)
            #pragma unroll
            for (int q = 0; q < 4; q++) acc[mt][nt][q] = 0.f;

    #pragma unroll
    for (int ks = 0; ks < 4; ++ks) {
        const int k0p = h32 + ks * 8 + 2 * tg;
        uint32_t a[2][4];
        #pragma unroll
        for (int mt = 0; mt < 2; mt++) {
            const int r0 = qb + mt * 16;
            float2 lo = *(const float2*)(gq_base + (long)(r0 + gq)     * QKVW + k0p);
            float2 hi = *(const float2*)(gq_base + (long)(r0 + gq + 8) * QKVW + k0p);
            a[mt][0] = __float_as_uint(lo.x);
            a[mt][1] = __float_as_uint(hi.x);
            a[mt][2] = __float_as_uint(lo.y);
            a[mt][3] = __float_as_uint(hi.y);
        }
        #pragma unroll
        for (int nt = 0; nt < 8; nt++) {
            float2 bv = *(const float2*)(gq_base + (long)(nt * 8 + gq) * QKVW + 256 + k0p);
            uint32_t b0 = __float_as_uint(bv.x);
            uint32_t b1 = __float_as_uint(bv.y);
            #pragma unroll
            for (int mt = 0; mt < 2; mt++)
                mma_tf32(acc[mt][nt], a[mt][0], a[mt][1], a[mt][2], a[mt][3], b0, b1);
        }
    }

    const float scale = 0.17677669529663687f;
    float* pl = s_attn + h * PL2;
    #pragma unroll
    for (int mt = 0; mt < 2; mt++) {
        #pragma unroll
        for (int nt = 0; nt < 8; nt++) {
            const int q0 = mt * 16 + gq, c = nt * 8 + 2 * tg;
            *(float2*)&pl[q0 * RS + c] =
                make_float2(acc[mt][nt][0] * scale, acc[mt][nt][1] * scale);
            *(float2*)&pl[(q0 + 8) * RS + c] =
                make_float2(acc[mt][nt][2] * scale, acc[mt][nt][3] * scale);
        }
    }
    __syncthreads();

    #pragma unroll 1
    for (int i = 0; i < 8; i++) {
        int pidx = tid + (i << 8);
        int q = pidx >> 6, k = pidx & 63;
        float av[8], m[8];
        #pragma unroll
        for (int hh = 0; hh < 8; hh++) av[hh] = s_attn[hh * PL2 + q * RS + k];
        #pragma unroll
        for (int hh = 0; hh < 8; hh++) {
            float s = 0.f;
            #pragma unroll
            for (int h2 = 0; h2 < 8; h2++) s += av[h2] * s_wpre[hh * 8 + h2];
            m[hh] = fast_exp(s);
        }
        #pragma unroll
        for (int hh = 0; hh < 8; hh++) s_attn[hh * PL2 + q * RS + k] = m[hh];
    }
    __syncthreads();

    {
        int q = tid >> 3, hh = tid & 7;
        float s = 0.f;
        #pragma unroll 8
        for (int k = 0; k < 64; k++) s += s_attn[hh * PL2 + q * RS + k];
        s_rsum[tid] = 1.0f / s;
    }
    __syncthreads();

    #pragma unroll 1
    for (int i = 0; i < 8; i++) {
        int pidx = tid + (i << 8);
        int q = pidx >> 6, k = pidx & 63;
        float av[8], m[8];
        #pragma unroll
        for (int hh = 0; hh < 8; hh++)
            av[hh] = s_attn[hh * PL2 + q * RS + k] * s_rsum[q * 8 + hh];
        #pragma unroll
        for (int hh = 0; hh < 8; hh++) {
            float s = 0.f;
            #pragma unroll
            for (int h2 = 0; h2 < 8; h2++) s += av[h2] * s_wpost[hh * 8 + h2];
            m[hh] = s;
        }
        #pragma unroll
        for (int hh = 0; hh < 8; hh++) s_attn[hh * PL2 + q * RS + k] = m[hh];
    }
    __syncthreads();

    float acc2[2][4][4];
    #pragma unroll
    for (int mt = 0; mt < 2; mt++)
        #pragma unroll
        for (int nt = 0; nt < 4; nt++)
            #pragma unroll
            for (int q = 0; q < 4; q++) acc2[mt][nt][q] = 0.f;

    #pragma unroll
    for (int ks = 0; ks < 8; ++ks) {
        const int k0 = ks * 8;
        uint32_t a[2][4];
        #pragma unroll
        for (int mt = 0; mt < 2; mt++) {
            const int r0 = mt * 16;
            a[mt][0] = f2tf(pl[(r0 + gq)     * RS + k0 + tg]);
            a[mt][1] = f2tf(pl[(r0 + gq + 8) * RS + k0 + tg]);
            a[mt][2] = f2tf(pl[(r0 + gq)     * RS + k0 + tg + 4]);
            a[mt][3] = f2tf(pl[(r0 + gq + 8) * RS + k0 + tg + 4]);
        }
        #pragma unroll
        for (int nt = 0; nt < 4; nt++) {
            const int nb = nt * 8;
            uint32_t b0 = __float_as_uint(
                gq_base[(long)(k0 + tg)     * QKVW + 512 + h32 + nb + gq]);
            uint32_t b1 = __float_as_uint(
                gq_base[(long)(k0 + tg + 4) * QKVW + 512 + h32 + nb + gq]);
            #pragma unroll
            for (int mt = 0; mt < 2; mt++)
                mma_tf32(acc2[mt][nt], a[mt][0], a[mt][1], a[mt][2], a[mt][3], b0, b1);
        }
    }

    #pragma unroll
    for (int mt = 0; mt < 2; mt++) {
        #pragma unroll
        for (int nt = 0; nt < 4; nt++) {
            const int col = h32 + nt * 8 + 2 * tg;
            const long r1 = rowbase + qb + mt * 16 + gq;
            *(float2*)(g_qkv + r1 * QKVW + col) =
                make_float2(ftf(acc2[mt][nt][0]), ftf(acc2[mt][nt][1]));
            *(float2*)(g_qkv + (r1 + 8) * QKVW + col) =
                make_float2(ftf(acc2[mt][nt][2]), ftf(acc2[mt][nt][3]));
        }
    }
}

// ---------------------------------------------------------------------------
// Kernel C: proj (R11: BN=128, grid-swapped, zero CVT).
// ---------------------------------------------------------------------------
#define PTS     36
#define PTILE_F (128 * PTS)
#define PBUF_F  (2 * PTILE_F)
#define SMEM_PROJ (2 * PBUF_F * 4)

__global__ __launch_bounds__(256) void proj_mma(
    const float* __restrict__ b_proj, float* __restrict__ out)
{
    extern __shared__ float sm[];
    const int tid = threadIdx.x;
    const long row0 = (long)blockIdx.y * 128;
    const int colb = blockIdx.x * 128;

    const int ldr = tid >> 1;
    const int ldc = (tid & 1) << 4;
    long row = row0 + ldr;
    int b = (int)(row >> 14);
    int n = (int)(row & 16383);
    int i = n >> 7, j = n & 127;
    int srcrow = ((b << 8) + (i >> 3) * 16 + (j >> 3)) * 64 + (i & 7) * 8 + (j & 7);
    const float* a_src0 = g_qkv + (long)srcrow * QKVW + ldc;
    const float* b_src0 = g_wproj + (long)(colb + ldr) * 256 + ldc;

    uint32_t smem_base = (uint32_t)__cvta_generic_to_shared(sm);
    uint32_t a_dst0 = smem_base + (uint32_t)(ldr * PTS + ldc) * 4;
    uint32_t b_dst0 = a_dst0 + PTILE_F * 4;

    const int lane = tid & 31, w = tid >> 5;
    const int wm = (w >> 1) * 32;
    const int wn = (w & 1) * 64;
    const int gq = lane >> 2, tg = lane & 3;

    float acc[2][8][4];
    #pragma unroll
    for (int mt = 0; mt < 2; mt++)
        #pragma unroll
        for (int nt = 0; nt < 8; nt++)
            #pragma unroll
            for (int q = 0; q < 4; q++) acc[mt][nt][q] = 0.f;

    {
        #pragma unroll
        for (int k = 0; k < 4; k++) CPA16(a_dst0 + k * 16, a_src0 + k * 4);
        #pragma unroll
        for (int k = 0; k < 4; k++) CPA16(b_dst0 + k * 16, b_src0 + k * 4);
        CP_COMMIT();
    }

    for (int kb = 0; kb < 8; ++kb) {
        CP_WAIT0();
        __syncthreads();
        if (kb < 7) {
            uint32_t off = (uint32_t)(((kb + 1) & 1) * PBUF_F * 4);
            const float* as = a_src0 + (kb + 1) * 32;
            const float* bs = b_src0 + (kb + 1) * 32;
            #pragma unroll
            for (int k = 0; k < 4; k++) CPA16(a_dst0 + off + k * 16, as + k * 4);
            #pragma unroll
            for (int k = 0; k < 4; k++) CPA16(b_dst0 + off + k * 16, bs + k * 4);
            CP_COMMIT();
        }
        const float* sA = sm + (kb & 1) * PBUF_F;
        const float* sB = sA + PTILE_F;

        #pragma unroll
        for (int ks = 0; ks < 4; ++ks) {
            const int k0 = ks * 8 + 2 * tg;
            uint32_t af[2][4];
            #pragma unroll
            for (int mt = 0; mt < 2; mt++) {
                const int r0 = wm + mt * 16;
                float2 lo = *(const float2*)&sA[(r0 + gq)     * PTS + k0];
                float2 hi = *(const float2*)&sA[(r0 + gq + 8) * PTS + k0];
                af[mt][0] = __float_as_uint(lo.x);
                af[mt][1] = __float_as_uint(hi.x);
                af[mt][2] = __float_as_uint(lo.y);
                af[mt][3] = __float_as_uint(hi.y);
            }
            #pragma unroll
            for (int nt = 0; nt < 8; nt++) {
                float2 bv = *(const float2*)&sB[(wn + nt * 8 + gq) * PTS + k0];
                uint32_t b0 = __float_as_uint(bv.x);
                uint32_t b1 = __float_as_uint(bv.y);
                mma_tf32(acc[0][nt], af[0][0], af[0][1], af[0][2], af[0][3], b0, b1);
                mma_tf32(acc[1][nt], af[1][0], af[1][1], af[1][2], af[1][3], b0, b1);
            }
        }
    }

    #pragma unroll
    for (int mt = 0; mt < 2; mt++) {
        #pragma unroll
        for (int nt = 0; nt < 8; nt++) {
            const int col = colb + wn + nt * 8 + tg * 2;
            const float2 bv = *(const float2*)(b_proj + col);
            const long r1 = row0 + wm + mt * 16 + gq;
            *(float2*)(out + r1 * NC + col) =
                make_float2(acc[mt][nt][0] + bv.x, acc[mt][nt][1] + bv.y);
            *(float2*)(out + (r1 + 8) * NC + col) =
                make_float2(acc[mt][nt][2] + bv.x, acc[mt][nt][3] + bv.y);
        }
    }
}

// ---------------------------------------------------------------------------
extern "C" void kernel_launch(void* const* d_in, const int* in_sizes, int n_in,
                              void* d_out, int out_size)
{
    const float* x      = (const float*)d_in[0];
    const float* query  = (const float*)d_in[1];
    const float* W_qk   = (const float*)d_in[2];
    const float* W_v    = (const float*)d_in[3];
    const float* W_proj = (const float*)d_in[4];
    const float* b_proj = (const float*)d_in[5];
    const float* W_pre  = (const float*)d_in[6];
    const float* W_post = (const float*)d_in[7];
    float* out = (float*)d_out;

    cudaFuncSetAttribute(qkv_mma, cudaFuncAttributeMaxDynamicSharedMemorySize, SMEM_G2);
    cudaFuncSetAttribute(attn_kernel, cudaFuncAttributeMaxDynamicSharedMemorySize, SMEM_ATTN_BYTES);
    cudaFuncSetAttribute(proj_mma, cudaFuncAttributeMaxDynamicSharedMemorySize, SMEM_PROJ);

    cvt_weights<<<128, 256>>>(W_qk, W_v, W_proj);
    qkv_mma<<<dim3(12, 1024), 256, SMEM_G2>>>(x, query);
    attn_kernel<<<NWIN * 2, 256, SMEM_ATTN_BYTES>>>(W_pre, W_post);
    proj_mma<<<dim3(2, 1024), 256, SMEM_PROJ>>>(b_proj, out);
}

// round 13
// speedup vs baseline: 1.0036x; 1.0036x over previous
#include <cuda_runtime.h>
#include <cstdint>

// Problem constants
#define NB    8
#define NTOK  16384
#define NC    256
#define NWIN  2048    // B * (16x16 windows)
#define QKVW  768     // q(256) | k(256) | v(256)

// g_qkv channel dims stored PERMUTED within 8-groups:
// position p holds channel c(p) = (p&1)*4 + (p>>1)   (order 0,4,1,5,2,6,3,7)
__device__ float g_qkv[(size_t)NWIN * 64 * QKVW];
__device__ float g_wqk[512 * 256];     // rounded + permuted cols (rows natural)
__device__ float g_wv[256 * 256];
__device__ float g_wproj[256 * 256];

// ---------------------------------------------------------------------------
__device__ __forceinline__ uint32_t f2tf(float f) {
    uint32_t u;
    asm("cvt.rna.tf32.f32 %0, %1;" : "=r"(u) : "f"(f));
    return u;
}
__device__ __forceinline__ float ftf(float f) {
    return __uint_as_float(f2tf(f));
}
__device__ __forceinline__ void mma_tf32(float c[4],
    uint32_t a0, uint32_t a1, uint32_t a2, uint32_t a3,
    uint32_t b0, uint32_t b1)
{
    asm volatile(
        "mma.sync.aligned.m16n8k8.row.col.f32.tf32.tf32.f32 "
        "{%0,%1,%2,%3},{%4,%5,%6,%7},{%8,%9},{%0,%1,%2,%3};"
        : "+f"(c[0]), "+f"(c[1]), "+f"(c[2]), "+f"(c[3])
        : "r"(a0), "r"(a1), "r"(a2), "r"(a3), "r"(b0), "r"(b1));
}
#define CPA16(dst, src) \
    asm volatile("cp.async.cg.shared.global [%0],[%1],16;" :: "r"(dst), "l"(src))
#define CP_COMMIT() asm volatile("cp.async.commit_group;")
#define CP_WAIT0()  asm volatile("cp.async.wait_group 0;" ::: "memory")

// qkv GEMM tiles: BM=128, BN=64, BK=32, 256 threads (8 warps of 32x32)
#define TS      36
#define ATILE_F (128 * TS)
#define BTILE_F (64 * TS)
#define BUF2_F  (ATILE_F + BTILE_F)
#define SMEM_G2 (2 * BUF2_F * 4)      // 55296 B -> 4 CTAs/SM

// ---------------------------------------------------------------------------
// Weights: round to tf32 + permute 8-groups (rows natural)
// ---------------------------------------------------------------------------
__global__ __launch_bounds__(256) void cvt_weights(
    const float* __restrict__ wqk, const float* __restrict__ wv,
    const float* __restrict__ wproj)
{
    const int t = blockIdx.x * 256 + threadIdx.x;
    const int off = t * 8;
    const float* s; float* d;
    if (off < 131072)      { s = wqk + off;           d = g_wqk + off; }
    else if (off < 196608) { s = wv + off - 131072;   d = g_wv + off - 131072; }
    else                   { s = wproj + off - 196608; d = g_wproj + off - 196608; }
    float4 v0 = ((const float4*)s)[0], v1 = ((const float4*)s)[1];
    ((float4*)d)[0] = make_float4(ftf(v0.x), ftf(v1.x), ftf(v0.y), ftf(v1.y));
    ((float4*)d)[1] = make_float4(ftf(v0.z), ftf(v1.z), ftf(v0.w), ftf(v1.w));
}

// ---------------------------------------------------------------------------
// Kernel A: Q|K|V GEMM (128x64 tile, 4 CTAs/SM). Grid-swapped so the 12 CTAs
// sharing one A tile co-run (A reads hit L2).
// ---------------------------------------------------------------------------
__global__ __launch_bounds__(256, 4) void qkv_mma(
    const float* __restrict__ x, const float* __restrict__ query)
{
    extern __shared__ float sm[];
    const int tid = threadIdx.x;
    const int cb  = blockIdx.x;     // 0..11
    const int p   = blockIdx.y;     // 0..1023

    const float* in = (cb < 8) ? query : x;
    const float* Wt = (cb < 8) ? (g_wqk + (long)cb * 64 * 256)
                               : (g_wv  + (long)(cb - 8) * 64 * 256);
    const int dstcol = (cb < 8) ? cb * 64 : 512 + (cb - 8) * 64;

    const int ldrA = tid >> 1, ldcA = (tid & 1) << 4;
    const int ldrB = tid >> 2, ldcB = (tid & 3) << 3;
    int win = p * 2 + (ldrA >> 6);
    int s   = ldrA & 63;
    int b   = win >> 8, g = win & 255;
    int n   = ((g >> 4) * 8 + (s >> 3)) * 128 + (g & 15) * 8 + (s & 7);
    const float* a_src0 = in + ((long)b * NTOK + n) * 256 + ldcA;
    const float* b_src0 = Wt + (long)ldrB * 256 + ldcB;

    uint32_t smem_base = (uint32_t)__cvta_generic_to_shared(sm);
    uint32_t a_dst0 = smem_base + (uint32_t)(ldrA * TS + ldcA) * 4;
    uint32_t b_dst0 = smem_base + (uint32_t)(ATILE_F + ldrB * TS + ldcB) * 4;

    const int lane = tid & 31, w = tid >> 5;
    const int wm = (w >> 1) * 32;
    const int wn = (w & 1) * 32;
    const int gq = lane >> 2, tg = lane & 3;

    float acc[2][4][4];
    #pragma unroll
    for (int mt = 0; mt < 2; mt++)
        #pragma unroll
        for (int nt = 0; nt < 4; nt++)
            #pragma unroll
            for (int q = 0; q < 4; q++) acc[mt][nt][q] = 0.f;

    {
        #pragma unroll
        for (int i = 0; i < 4; i++) CPA16(a_dst0 + i * 16, a_src0 + i * 4);
        #pragma unroll
        for (int i = 0; i < 2; i++) CPA16(b_dst0 + i * 16, b_src0 + i * 4);
        CP_COMMIT();
    }

    for (int kb = 0; kb < 8; ++kb) {
        CP_WAIT0();
        __syncthreads();
        if (kb < 7) {
            uint32_t off = (uint32_t)(((kb + 1) & 1) * BUF2_F * 4);
            const float* as = a_src0 + (kb + 1) * 32;
            const float* bs = b_src0 + (kb + 1) * 32;
            #pragma unroll
            for (int i = 0; i < 4; i++) CPA16(a_dst0 + off + i * 16, as + i * 4);
            #pragma unroll
            for (int i = 0; i < 2; i++) CPA16(b_dst0 + off + i * 16, bs + i * 4);
            CP_COMMIT();
        }
        const float* sA = sm + (kb & 1) * BUF2_F;
        const float* sB = sA + ATILE_F;

        #pragma unroll
        for (int ks = 0; ks < 4; ++ks) {
            const int k0n = ks * 8;
            const int k0p = ks * 8 + 2 * tg;
            uint32_t af[2][4];
            #pragma unroll
            for (int mt = 0; mt < 2; mt++) {
                const int r0 = wm + mt * 16;
                af[mt][0] = f2tf(sA[(r0 + gq)     * TS + k0n + tg]);
                af[mt][1] = f2tf(sA[(r0 + gq + 8) * TS + k0n + tg]);
                af[mt][2] = f2tf(sA[(r0 + gq)     * TS + k0n + tg + 4]);
                af[mt][3] = f2tf(sA[(r0 + gq + 8) * TS + k0n + tg + 4]);
            }
            #pragma unroll
            for (int nt = 0; nt < 4; nt++) {
                float2 bv = *(const float2*)&sB[(wn + nt * 8 + gq) * TS + k0p];
                uint32_t b0 = __float_as_uint(bv.x);
                uint32_t b1 = __float_as_uint(bv.y);
                mma_tf32(acc[0][nt], af[0][0], af[0][1], af[0][2], af[0][3], b0, b1);
                mma_tf32(acc[1][nt], af[1][0], af[1][1], af[1][2], af[1][3], b0, b1);
            }
        }
    }

    const long row0 = (long)p * 128;
    const int pb = (tg & 1) * 4 + (tg >> 1);
    #pragma unroll
    for (int mt = 0; mt < 2; mt++) {
        #pragma unroll
        for (int nt = 0; nt < 4; nt++) {
            const int gb = dstcol + wn + nt * 8;
            const long r1 = row0 + wm + mt * 16 + gq;
            g_qkv[r1 * QKVW + gb + pb]           = ftf(acc[mt][nt][0]);
            g_qkv[r1 * QKVW + gb + pb + 2]       = ftf(acc[mt][nt][1]);
            g_qkv[(r1 + 8) * QKVW + gb + pb]     = ftf(acc[mt][nt][2]);
            g_qkv[(r1 + 8) * QKVW + gb + pb + 2] = ftf(acc[mt][nt][3]);
        }
    }
}

// ---------------------------------------------------------------------------
// Kernel B: attention — R11 verbatim BUT __launch_bounds__(256, 2) to cap
// registers at 128 and get 2 CTAs/SM (reg-occupancy was the suspected wall).
// ---------------------------------------------------------------------------
#define PL2 2116
#define RS  66
#define OFF_WPRE  (8 * PL2)
#define OFF_WPOST (OFF_WPRE + 64)
#define OFF_RSUM  (OFF_WPRE + 128)
#define SMEM_ATTN_BYTES ((OFF_RSUM + 256) * 4)

__global__ __launch_bounds__(256, 2) void attn_kernel(
    const float* __restrict__ W_pre, const float* __restrict__ W_post)
{
    extern __shared__ float sm[];
    float* s_attn  = sm;
    float* s_wpre  = sm + OFF_WPRE;
    float* s_wpost = sm + OFF_WPOST;
    float* s_rsum  = sm + OFF_RSUM;

    const int tid  = threadIdx.x;
    const int lane = tid & 31;
    const int h    = tid >> 5;
    const int gq = lane >> 2, tg = lane & 3;
    const int h32 = h * 32;
    const int win = blockIdx.x >> 1;
    const int qb  = (blockIdx.x & 1) * 32;
    const long rowbase = (long)win * 64;
    const float* gq_base = g_qkv + rowbase * QKVW;

    if (tid < 64) { s_wpre[tid] = W_pre[tid]; s_wpost[tid] = W_post[tid]; }

    float acc[2][8][4];
    #pragma unroll
    for (int mt = 0; mt < 2; mt++)
        #pragma unroll
        for (int nt = 0; nt < 8; nt++)
            #pragma unroll
            for (int q = 0; q < 4; q++) acc[mt][nt][q] = 0.f;

    #pragma unroll
    for (int ks = 0; ks < 4; ++ks) {
        const int k0p = h32 + ks * 8 + 2 * tg;
        uint32_t a[2][4];
        #pragma unroll
        for (int mt = 0; mt < 2; mt++) {
            const int r0 = qb + mt * 16;
            float2 lo = *(const float2*)(gq_base + (long)(r0 + gq)     * QKVW + k0p);
            float2 hi = *(const float2*)(gq_base + (long)(r0 + gq + 8) * QKVW + k0p);
            a[mt][0] = __float_as_uint(lo.x);
            a[mt][1] = __float_as_uint(hi.x);
            a[mt][2] = __float_as_uint(lo.y);
            a[mt][3] = __float_as_uint(hi.y);
        }
        #pragma unroll
        for (int nt = 0; nt < 8; nt++) {
            float2 bv = *(const float2*)(gq_base + (long)(nt * 8 + gq) * QKVW + 256 + k0p);
            uint32_t b0 = __float_as_uint(bv.x);
            uint32_t b1 = __float_as_uint(bv.y);
            #pragma unroll
            for (int mt = 0; mt < 2; mt++)
                mma_tf32(acc[mt][nt], a[mt][0], a[mt][1], a[mt][2], a[mt][3], b0, b1);
        }
    }

    const float scale = 0.17677669529663687f;
    float* pl = s_attn + h * PL2;
    #pragma unroll
    for (int mt = 0; mt < 2; mt++) {
        #pragma unroll
        for (int nt = 0; nt < 8; nt++) {
            const int q0 = mt * 16 + gq, c = nt * 8 + 2 * tg;
            *(float2*)&pl[q0 * RS + c] =
                make_float2(acc[mt][nt][0] * scale, acc[mt][nt][1] * scale);
            *(float2*)&pl[(q0 + 8) * RS + c] =
                make_float2(acc[mt][nt][2] * scale, acc[mt][nt][3] * scale);
        }
    }
    __syncthreads();

    #pragma unroll 1
    for (int i = 0; i < 8; i++) {
        int pidx = tid + (i << 8);
        int q = pidx >> 6, k = pidx & 63;
        float av[8], m[8];
        #pragma unroll
        for (int hh = 0; hh < 8; hh++) av[hh] = s_attn[hh * PL2 + q * RS + k];
        #pragma unroll
        for (int hh = 0; hh < 8; hh++) {
            float s = 0.f;
            #pragma unroll
            for (int h2 = 0; h2 < 8; h2++) s += av[h2] * s_wpre[hh * 8 + h2];
            m[hh] = __expf(s);
        }
        #pragma unroll
        for (int hh = 0; hh < 8; hh++) s_attn[hh * PL2 + q * RS + k] = m[hh];
    }
    __syncthreads();

    {
        int q = tid >> 3, hh = tid & 7;
        float s = 0.f;
        #pragma unroll 8
        for (int k = 0; k < 64; k++) s += s_attn[hh * PL2 + q * RS + k];
        s_rsum[tid] = 1.0f / s;
    }
    __syncthreads();

    #pragma unroll 1
    for (int i = 0; i < 8; i++) {
        int pidx = tid + (i << 8);
        int q = pidx >> 6, k = pidx & 63;
        float av[8], m[8];
        #pragma unroll
        for (int hh = 0; hh < 8; hh++)
            av[hh] = s_attn[hh * PL2 + q * RS + k] * s_rsum[q * 8 + hh];
        #pragma unroll
        for (int hh = 0; hh < 8; hh++) {
            float s = 0.f;
            #pragma unroll
            for (int h2 = 0; h2 < 8; h2++) s += av[h2] * s_wpost[hh * 8 + h2];
            m[hh] = s;
        }
        #pragma unroll
        for (int hh = 0; hh < 8; hh++) s_attn[hh * PL2 + q * RS + k] = m[hh];
    }
    __syncthreads();

    float acc2[2][4][4];
    #pragma unroll
    for (int mt = 0; mt < 2; mt++)
        #pragma unroll
        for (int nt = 0; nt < 4; nt++)
            #pragma unroll
            for (int q = 0; q < 4; q++) acc2[mt][nt][q] = 0.f;

    #pragma unroll
    for (int ks = 0; ks < 8; ++ks) {
        const int k0 = ks * 8;
        uint32_t a[2][4];
        #pragma unroll
        for (int mt = 0; mt < 2; mt++) {
            const int r0 = mt * 16;
            a[mt][0] = f2tf(pl[(r0 + gq)     * RS + k0 + tg]);
            a[mt][1] = f2tf(pl[(r0 + gq + 8) * RS + k0 + tg]);
            a[mt][2] = f2tf(pl[(r0 + gq)     * RS + k0 + tg + 4]);
            a[mt][3] = f2tf(pl[(r0 + gq + 8) * RS + k0 + tg + 4]);
        }
        #pragma unroll
        for (int nt = 0; nt < 4; nt++) {
            const int nb = nt * 8;
            uint32_t b0 = __float_as_uint(
                gq_base[(long)(k0 + tg)     * QKVW + 512 + h32 + nb + gq]);
            uint32_t b1 = __float_as_uint(
                gq_base[(long)(k0 + tg + 4) * QKVW + 512 + h32 + nb + gq]);
            #pragma unroll
            for (int mt = 0; mt < 2; mt++)
                mma_tf32(acc2[mt][nt], a[mt][0], a[mt][1], a[mt][2], a[mt][3], b0, b1);
        }
    }

    #pragma unroll
    for (int mt = 0; mt < 2; mt++) {
        #pragma unroll
        for (int nt = 0; nt < 4; nt++) {
            const int col = h32 + nt * 8 + 2 * tg;
            const long r1 = rowbase + qb + mt * 16 + gq;
            *(float2*)(g_qkv + r1 * QKVW + col) =
                make_float2(ftf(acc2[mt][nt][0]), ftf(acc2[mt][nt][1]));
            *(float2*)(g_qkv + (r1 + 8) * QKVW + col) =
                make_float2(ftf(acc2[mt][nt][2]), ftf(acc2[mt][nt][3]));
        }
    }
}

// ---------------------------------------------------------------------------
// Kernel C: proj (BN=128, grid-swapped, zero CVT).
// ---------------------------------------------------------------------------
#define PTS     36
#define PTILE_F (128 * PTS)
#define PBUF_F  (2 * PTILE_F)
#define SMEM_PROJ (2 * PBUF_F * 4)

__global__ __launch_bounds__(256) void proj_mma(
    const float* __restrict__ b_proj, float* __restrict__ out)
{
    extern __shared__ float sm[];
    const int tid = threadIdx.x;
    const long row0 = (long)blockIdx.y * 128;
    const int colb = blockIdx.x * 128;

    const int ldr = tid >> 1;
    const int ldc = (tid & 1) << 4;
    long row = row0 + ldr;
    int b = (int)(row >> 14);
    int n = (int)(row & 16383);
    int i = n >> 7, j = n & 127;
    int srcrow = ((b << 8) + (i >> 3) * 16 + (j >> 3)) * 64 + (i & 7) * 8 + (j & 7);
    const float* a_src0 = g_qkv + (long)srcrow * QKVW + ldc;
    const float* b_src0 = g_wproj + (long)(colb + ldr) * 256 + ldc;

    uint32_t smem_base = (uint32_t)__cvta_generic_to_shared(sm);
    uint32_t a_dst0 = smem_base + (uint32_t)(ldr * PTS + ldc) * 4;
    uint32_t b_dst0 = a_dst0 + PTILE_F * 4;

    const int lane = tid & 31, w = tid >> 5;
    const int wm = (w >> 1) * 32;
    const int wn = (w & 1) * 64;
    const int gq = lane >> 2, tg = lane & 3;

    float acc[2][8][4];
    #pragma unroll
    for (int mt = 0; mt < 2; mt++)
        #pragma unroll
        for (int nt = 0; nt < 8; nt++)
            #pragma unroll
            for (int q = 0; q < 4; q++) acc[mt][nt][q] = 0.f;

    {
        #pragma unroll
        for (int k = 0; k < 4; k++) CPA16(a_dst0 + k * 16, a_src0 + k * 4);
        #pragma unroll
        for (int k = 0; k < 4; k++) CPA16(b_dst0 + k * 16, b_src0 + k * 4);
        CP_COMMIT();
    }

    for (int kb = 0; kb < 8; ++kb) {
        CP_WAIT0();
        __syncthreads();
        if (kb < 7) {
            uint32_t off = (uint32_t)(((kb + 1) & 1) * PBUF_F * 4);
            const float* as = a_src0 + (kb + 1) * 32;
            const float* bs = b_src0 + (kb + 1) * 32;
            #pragma unroll
            for (int k = 0; k < 4; k++) CPA16(a_dst0 + off + k * 16, as + k * 4);
            #pragma unroll
            for (int k = 0; k < 4; k++) CPA16(b_dst0 + off + k * 16, bs + k * 4);
            CP_COMMIT();
        }
        const float* sA = sm + (kb & 1) * PBUF_F;
        const float* sB = sA + PTILE_F;

        #pragma unroll
        for (int ks = 0; ks < 4; ++ks) {
            const int k0 = ks * 8 + 2 * tg;
            uint32_t af[2][4];
            #pragma unroll
            for (int mt = 0; mt < 2; mt++) {
                const int r0 = wm + mt * 16;
                float2 lo = *(const float2*)&sA[(r0 + gq)     * PTS + k0];
                float2 hi = *(const float2*)&sA[(r0 + gq + 8) * PTS + k0];
                af[mt][0] = __float_as_uint(lo.x);
                af[mt][1] = __float_as_uint(hi.x);
                af[mt][2] = __float_as_uint(lo.y);
                af[mt][3] = __float_as_uint(hi.y);
            }
            #pragma unroll
            for (int nt = 0; nt < 8; nt++) {
                float2 bv = *(const float2*)&sB[(wn + nt * 8 + gq) * PTS + k0];
                uint32_t b0 = __float_as_uint(bv.x);
                uint32_t b1 = __float_as_uint(bv.y);
                mma_tf32(acc[0][nt], af[0][0], af[0][1], af[0][2], af[0][3], b0, b1);
                mma_tf32(acc[1][nt], af[1][0], af[1][1], af[1][2], af[1][3], b0, b1);
            }
        }
    }

    #pragma unroll
    for (int mt = 0; mt < 2; mt++) {
        #pragma unroll
        for (int nt = 0; nt < 8; nt++) {
            const int col = colb + wn + nt * 8 + tg * 2;
            const float2 bv = *(const float2*)(b_proj + col);
            const long r1 = row0 + wm + mt * 16 + gq;
            *(float2*)(out + r1 * NC + col) =
                make_float2(acc[mt][nt][0] + bv.x, acc[mt][nt][1] + bv.y);
            *(float2*)(out + (r1 + 8) * NC + col) =
                make_float2(acc[mt][nt][2] + bv.x, acc[mt][nt][3] + bv.y);
        }
    }
}

// ---------------------------------------------------------------------------
extern "C" void kernel_launch(void* const* d_in, const int* in_sizes, int n_in,
                              void* d_out, int out_size)
{
    const float* x      = (const float*)d_in[0];
    const float* query  = (const float*)d_in[1];
    const float* W_qk   = (const float*)d_in[2];
    const float* W_v    = (const float*)d_in[3];
    const float* W_proj = (const float*)d_in[4];
    const float* b_proj = (const float*)d_in[5];
    const float* W_pre  = (const float*)d_in[6];
    const float* W_post = (const float*)d_in[7];
    float* out = (float*)d_out;

    cudaFuncSetAttribute(qkv_mma, cudaFuncAttributeMaxDynamicSharedMemorySize, SMEM_G2);
    cudaFuncSetAttribute(attn_kernel, cudaFuncAttributeMaxDynamicSharedMemorySize, SMEM_ATTN_BYTES);
    cudaFuncSetAttribute(proj_mma, cudaFuncAttributeMaxDynamicSharedMemorySize, SMEM_PROJ);

    cvt_weights<<<128, 256>>>(W_qk, W_v, W_proj);
    qkv_mma<<<dim3(12, 1024), 256, SMEM_G2>>>(x, query);
    attn_kernel<<<NWIN * 2, 256, SMEM_ATTN_BYTES>>>(W_pre, W_post);
    proj_mma<<<dim3(2, 1024), 256, SMEM_PROJ>>>(b_proj, out);
}

// round 14
// speedup vs baseline: 1.0370x; 1.0333x over previous
#include <cuda_runtime.h>
#include <cstdint>

// Problem constants
#define NB    8
#define NTOK  16384
#define NC    256
#define NWIN  2048    // B * (16x16 windows)
#define QKVW  768     // q(256) | k(256) | v(256)

// g_qkv channel dims stored PERMUTED within 8-groups:
// position p holds channel c(p) = (p&1)*4 + (p>>1)   (order 0,4,1,5,2,6,3,7)
__device__ float g_qkv[(size_t)NWIN * 64 * QKVW];
__device__ float g_wqk[512 * 256];     // rounded + permuted cols (rows natural)
__device__ float g_wv[256 * 256];
__device__ float g_wproj[256 * 256];

// ---------------------------------------------------------------------------
__device__ __forceinline__ uint32_t f2tf(float f) {
    uint32_t u;
    asm("cvt.rna.tf32.f32 %0, %1;" : "=r"(u) : "f"(f));
    return u;
}
__device__ __forceinline__ float ftf(float f) {
    return __uint_as_float(f2tf(f));
}
__device__ __forceinline__ void mma_tf32(float c[4],
    uint32_t a0, uint32_t a1, uint32_t a2, uint32_t a3,
    uint32_t b0, uint32_t b1)
{
    asm volatile(
        "mma.sync.aligned.m16n8k8.row.col.f32.tf32.tf32.f32 "
        "{%0,%1,%2,%3},{%4,%5,%6,%7},{%8,%9},{%0,%1,%2,%3};"
        : "+f"(c[0]), "+f"(c[1]), "+f"(c[2]), "+f"(c[3])
        : "r"(a0), "r"(a1), "r"(a2), "r"(a3), "r"(b0), "r"(b1));
}
#define CPA16(dst, src) \
    asm volatile("cp.async.cg.shared.global [%0],[%1],16;" :: "r"(dst), "l"(src))
#define CP_COMMIT() asm volatile("cp.async.commit_group;")
#define CP_WAIT0()  asm volatile("cp.async.wait_group 0;" ::: "memory")

// qkv GEMM tiles: BM=128, BN=64, BK=32, 256 threads (8 warps of 32x32)
#define TS      36
#define ATILE_F (128 * TS)
#define BTILE_F (64 * TS)
#define BUF2_F  (ATILE_F + BTILE_F)
#define SMEM_G2 (2 * BUF2_F * 4)      // 55296 B -> 4 CTAs/SM

// ---------------------------------------------------------------------------
// Weights: round to tf32 + permute 8-groups (rows natural)
// ---------------------------------------------------------------------------
__global__ __launch_bounds__(256) void cvt_weights(
    const float* __restrict__ wqk, const float* __restrict__ wv,
    const float* __restrict__ wproj)
{
    const int t = blockIdx.x * 256 + threadIdx.x;
    const int off = t * 8;
    const float* s; float* d;
    if (off < 131072)      { s = wqk + off;           d = g_wqk + off; }
    else if (off < 196608) { s = wv + off - 131072;   d = g_wv + off - 131072; }
    else                   { s = wproj + off - 196608; d = g_wproj + off - 196608; }
    float4 v0 = ((const float4*)s)[0], v1 = ((const float4*)s)[1];
    ((float4*)d)[0] = make_float4(ftf(v0.x), ftf(v1.x), ftf(v0.y), ftf(v1.y));
    ((float4*)d)[1] = make_float4(ftf(v0.z), ftf(v1.z), ftf(v0.w), ftf(v1.w));
}

// ---------------------------------------------------------------------------
// Kernel A: Q|K|V GEMM (128x64 tile, 4 CTAs/SM). Grid-swapped so the 12 CTAs
// sharing one A tile co-run (A reads hit L2).
// ---------------------------------------------------------------------------
__global__ __launch_bounds__(256, 4) void qkv_mma(
    const float* __restrict__ x, const float* __restrict__ query)
{
    extern __shared__ float sm[];
    const int tid = threadIdx.x;
    const int cb  = blockIdx.x;     // 0..11
    const int p   = blockIdx.y;     // 0..1023

    const float* in = (cb < 8) ? query : x;
    const float* Wt = (cb < 8) ? (g_wqk + (long)cb * 64 * 256)
                               : (g_wv  + (long)(cb - 8) * 64 * 256);
    const int dstcol = (cb < 8) ? cb * 64 : 512 + (cb - 8) * 64;

    const int ldrA = tid >> 1, ldcA = (tid & 1) << 4;
    const int ldrB = tid >> 2, ldcB = (tid & 3) << 3;
    int win = p * 2 + (ldrA >> 6);
    int s   = ldrA & 63;
    int b   = win >> 8, g = win & 255;
    int n   = ((g >> 4) * 8 + (s >> 3)) * 128 + (g & 15) * 8 + (s & 7);
    const float* a_src0 = in + ((long)b * NTOK + n) * 256 + ldcA;
    const float* b_src0 = Wt + (long)ldrB * 256 + ldcB;

    uint32_t smem_base = (uint32_t)__cvta_generic_to_shared(sm);
    uint32_t a_dst0 = smem_base + (uint32_t)(ldrA * TS + ldcA) * 4;
    uint32_t b_dst0 = smem_base + (uint32_t)(ATILE_F + ldrB * TS + ldcB) * 4;

    const int lane = tid & 31, w = tid >> 5;
    const int wm = (w >> 1) * 32;
    const int wn = (w & 1) * 32;
    const int gq = lane >> 2, tg = lane & 3;

    float acc[2][4][4];
    #pragma unroll
    for (int mt = 0; mt < 2; mt++)
        #pragma unroll
        for (int nt = 0; nt < 4; nt++)
            #pragma unroll
            for (int q = 0; q < 4; q++) acc[mt][nt][q] = 0.f;

    {
        #pragma unroll
        for (int i = 0; i < 4; i++) CPA16(a_dst0 + i * 16, a_src0 + i * 4);
        #pragma unroll
        for (int i = 0; i < 2; i++) CPA16(b_dst0 + i * 16, b_src0 + i * 4);
        CP_COMMIT();
    }

    for (int kb = 0; kb < 8; ++kb) {
        CP_WAIT0();
        __syncthreads();
        if (kb < 7) {
            uint32_t off = (uint32_t)(((kb + 1) & 1) * BUF2_F * 4);
            const float* as = a_src0 + (kb + 1) * 32;
            const float* bs = b_src0 + (kb + 1) * 32;
            #pragma unroll
            for (int i = 0; i < 4; i++) CPA16(a_dst0 + off + i * 16, as + i * 4);
            #pragma unroll
            for (int i = 0; i < 2; i++) CPA16(b_dst0 + off + i * 16, bs + i * 4);
            CP_COMMIT();
        }
        const float* sA = sm + (kb & 1) * BUF2_F;
        const float* sB = sA + ATILE_F;

        #pragma unroll
        for (int ks = 0; ks < 4; ++ks) {
            const int k0n = ks * 8;
            const int k0p = ks * 8 + 2 * tg;
            uint32_t af[2][4];
            #pragma unroll
            for (int mt = 0; mt < 2; mt++) {
                const int r0 = wm + mt * 16;
                af[mt][0] = f2tf(sA[(r0 + gq)     * TS + k0n + tg]);
                af[mt][1] = f2tf(sA[(r0 + gq + 8) * TS + k0n + tg]);
                af[mt][2] = f2tf(sA[(r0 + gq)     * TS + k0n + tg + 4]);
                af[mt][3] = f2tf(sA[(r0 + gq + 8) * TS + k0n + tg + 4]);
            }
            #pragma unroll
            for (int nt = 0; nt < 4; nt++) {
                float2 bv = *(const float2*)&sB[(wn + nt * 8 + gq) * TS + k0p];
                uint32_t b0 = __float_as_uint(bv.x);
                uint32_t b1 = __float_as_uint(bv.y);
                mma_tf32(acc[0][nt], af[0][0], af[0][1], af[0][2], af[0][3], b0, b1);
                mma_tf32(acc[1][nt], af[1][0], af[1][1], af[1][2], af[1][3], b0, b1);
            }
        }
    }

    const long row0 = (long)p * 128;
    const int pb = (tg & 1) * 4 + (tg >> 1);
    #pragma unroll
    for (int mt = 0; mt < 2; mt++) {
        #pragma unroll
        for (int nt = 0; nt < 4; nt++) {
            const int gb = dstcol + wn + nt * 8;
            const long r1 = row0 + wm + mt * 16 + gq;
            g_qkv[r1 * QKVW + gb + pb]           = ftf(acc[mt][nt][0]);
            g_qkv[r1 * QKVW + gb + pb + 2]       = ftf(acc[mt][nt][1]);
            g_qkv[(r1 + 8) * QKVW + gb + pb]     = ftf(acc[mt][nt][2]);
            g_qkv[(r1 + 8) * QKVW + gb + pb + 2] = ftf(acc[mt][nt][3]);
        }
    }
}

// ---------------------------------------------------------------------------
// Kernel B: attention. Scores + O via mma (as R11). NEW: both talking-heads
// mixes are ALSO mma (heads = contracted dim, W_pre/W_post held in 2 regs),
// exp applied in registers. Warp w owns rows [w*256, w*256+256) of the 2048
// (q,k) pairs; in-place plane update is race-free (disjoint row ranges,
// mma.sync orders intra-warp LDS before STS).
// ---------------------------------------------------------------------------
#define PL2 2120             // plane stride; mod 32 == 8 -> conflict-free mix A
#define RS  66
#define OFF_WPRE  (8 * PL2)
#define OFF_WPOST (OFF_WPRE + 64)
#define OFF_RSUM  (OFF_WPRE + 128)
#define SMEM_ATTN_BYTES ((OFF_RSUM + 256) * 4)

__global__ __launch_bounds__(256) void attn_kernel(
    const float* __restrict__ W_pre, const float* __restrict__ W_post)
{
    extern __shared__ float sm[];
    float* s_attn  = sm;
    float* s_wpre  = sm + OFF_WPRE;
    float* s_wpost = sm + OFF_WPOST;
    float* s_rsum  = sm + OFF_RSUM;

    const int tid  = threadIdx.x;
    const int lane = tid & 31;
    const int h    = tid >> 5;
    const int gq = lane >> 2, tg = lane & 3;
    const int h32 = h * 32;
    const int win = blockIdx.x >> 1;
    const int qb  = (blockIdx.x & 1) * 32;
    const long rowbase = (long)win * 64;
    const float* gq_base = g_qkv + rowbase * QKVW;

    if (tid < 64) { s_wpre[tid] = W_pre[tid]; s_wpost[tid] = W_post[tid]; }

    // ---- scores: S_h = Q_h @ K_h^T  (M=32, N=64, K=32) — direct LDG ----
    float acc[2][8][4];
    #pragma unroll
    for (int mt = 0; mt < 2; mt++)
        #pragma unroll
        for (int nt = 0; nt < 8; nt++)
            #pragma unroll
            for (int q = 0; q < 4; q++) acc[mt][nt][q] = 0.f;

    #pragma unroll
    for (int ks = 0; ks < 4; ++ks) {
        const int k0p = h32 + ks * 8 + 2 * tg;
        uint32_t a[2][4];
        #pragma unroll
        for (int mt = 0; mt < 2; mt++) {
            const int r0 = qb + mt * 16;
            float2 lo = *(const float2*)(gq_base + (long)(r0 + gq)     * QKVW + k0p);
            float2 hi = *(const float2*)(gq_base + (long)(r0 + gq + 8) * QKVW + k0p);
            a[mt][0] = __float_as_uint(lo.x);
            a[mt][1] = __float_as_uint(hi.x);
            a[mt][2] = __float_as_uint(lo.y);
            a[mt][3] = __float_as_uint(hi.y);
        }
        #pragma unroll
        for (int nt = 0; nt < 8; nt++) {
            float2 bv = *(const float2*)(gq_base + (long)(nt * 8 + gq) * QKVW + 256 + k0p);
            uint32_t b0 = __float_as_uint(bv.x);
            uint32_t b1 = __float_as_uint(bv.y);
            #pragma unroll
            for (int mt = 0; mt < 2; mt++)
                mma_tf32(acc[mt][nt], a[mt][0], a[mt][1], a[mt][2], a[mt][3], b0, b1);
        }
    }

    // STS scaled + tf32-rounded scores (so the mix mma's A needs no CVT)
    const float scale = 0.17677669529663687f;
    float* pl = s_attn + h * PL2;
    #pragma unroll
    for (int mt = 0; mt < 2; mt++) {
        #pragma unroll
        for (int nt = 0; nt < 8; nt++) {
            const int q0 = mt * 16 + gq, c = nt * 8 + 2 * tg;
            *(float2*)&pl[q0 * RS + c] =
                make_float2(ftf(acc[mt][nt][0] * scale), ftf(acc[mt][nt][1] * scale));
            *(float2*)&pl[(q0 + 8) * RS + c] =
                make_float2(ftf(acc[mt][nt][2] * scale), ftf(acc[mt][nt][3] * scale));
        }
    }
    __syncthreads();

    // ---- pre-mix (tensor) + exp: warp w handles rows [w*256, w*256+256) ----
    {
        const uint32_t wb0 = f2tf(s_wpre[gq * 8 + tg]);
        const uint32_t wb1 = f2tf(s_wpre[gq * 8 + tg + 4]);
        #pragma unroll 4
        for (int i = 0; i < 16; ++i) {
            const int r0 = h * 128 + i * 16 + (h & 1) * 0; // rows base (see below)
            // NOTE: 8 warps x 256 rows = 2048; base = h*256
            const int rb = h * 256 + i * 16;
            const int q = rb >> 6, kk = (rb & 63) + gq;
            (void)r0;
            uint32_t a0 = __float_as_uint(s_attn[tg * PL2 + q * RS + kk]);
            uint32_t a1 = __float_as_uint(s_attn[tg * PL2 + q * RS + kk + 8]);
            uint32_t a2 = __float_as_uint(s_attn[(tg + 4) * PL2 + q * RS + kk]);
            uint32_t a3 = __float_as_uint(s_attn[(tg + 4) * PL2 + q * RS + kk + 8]);
            float c[4] = {0.f, 0.f, 0.f, 0.f};
            mma_tf32(c, a0, a1, a2, a3, wb0, wb1);
            s_attn[(2 * tg)     * PL2 + q * RS + kk]     = __expf(c[0]);
            s_attn[(2 * tg + 1) * PL2 + q * RS + kk]     = __expf(c[1]);
            s_attn[(2 * tg)     * PL2 + q * RS + kk + 8] = __expf(c[2]);
            s_attn[(2 * tg + 1) * PL2 + q * RS + kk + 8] = __expf(c[3]);
        }
    }
    __syncthreads();

    // ---- softmax denominator (256 tasks = 32q x 8h) ----
    {
        int q = tid >> 3, hh = tid & 7;
        float s = 0.f;
        #pragma unroll 8
        for (int k = 0; k < 64; k++) s += s_attn[hh * PL2 + q * RS + k];
        s_rsum[tid] = 1.0f / s;
    }
    __syncthreads();

    // ---- post-mix (tensor): normalize A by rsum, mix with W_post ----
    {
        const uint32_t wb0 = f2tf(s_wpost[gq * 8 + tg]);
        const uint32_t wb1 = f2tf(s_wpost[gq * 8 + tg + 4]);
        #pragma unroll 4
        for (int i = 0; i < 16; ++i) {
            const int rb = h * 256 + i * 16;
            const int q = rb >> 6, kk = (rb & 63) + gq;
            const float rs0 = s_rsum[q * 8 + tg];
            const float rs1 = s_rsum[q * 8 + tg + 4];
            uint32_t a0 = f2tf(s_attn[tg * PL2 + q * RS + kk] * rs0);
            uint32_t a1 = f2tf(s_attn[tg * PL2 + q * RS + kk + 8] * rs0);
            uint32_t a2 = f2tf(s_attn[(tg + 4) * PL2 + q * RS + kk] * rs1);
            uint32_t a3 = f2tf(s_attn[(tg + 4) * PL2 + q * RS + kk + 8] * rs1);
            float c[4] = {0.f, 0.f, 0.f, 0.f};
            mma_tf32(c, a0, a1, a2, a3, wb0, wb1);
            s_attn[(2 * tg)     * PL2 + q * RS + kk]     = c[0];
            s_attn[(2 * tg + 1) * PL2 + q * RS + kk]     = c[1];
            s_attn[(2 * tg)     * PL2 + q * RS + kk + 8] = c[2];
            s_attn[(2 * tg + 1) * PL2 + q * RS + kk + 8] = c[3];
        }
    }
    __syncthreads();

    // ---- O_h = A_h @ V_h (M=32, N=32, K=64) — V direct LDG (rounded) ----
    float acc2[2][4][4];
    #pragma unroll
    for (int mt = 0; mt < 2; mt++)
        #pragma unroll
        for (int nt = 0; nt < 4; nt++)
            #pragma unroll
            for (int q = 0; q < 4; q++) acc2[mt][nt][q] = 0.f;

    #pragma unroll
    for (int ks = 0; ks < 8; ++ks) {
        const int k0 = ks * 8;
        uint32_t a[2][4];
        #pragma unroll
        for (int mt = 0; mt < 2; mt++) {
            const int r0 = mt * 16;
            a[mt][0] = f2tf(pl[(r0 + gq)     * RS + k0 + tg]);
            a[mt][1] = f2tf(pl[(r0 + gq + 8) * RS + k0 + tg]);
            a[mt][2] = f2tf(pl[(r0 + gq)     * RS + k0 + tg + 4]);
            a[mt][3] = f2tf(pl[(r0 + gq + 8) * RS + k0 + tg + 4]);
        }
        #pragma unroll
        for (int nt = 0; nt < 4; nt++) {
            const int nb = nt * 8;
            uint32_t b0 = __float_as_uint(
                gq_base[(long)(k0 + tg)     * QKVW + 512 + h32 + nb + gq]);
            uint32_t b1 = __float_as_uint(
                gq_base[(long)(k0 + tg + 4) * QKVW + 512 + h32 + nb + gq]);
            #pragma unroll
            for (int mt = 0; mt < 2; mt++)
                mma_tf32(acc2[mt][nt], a[mt][0], a[mt][1], a[mt][2], a[mt][3], b0, b1);
        }
    }

    #pragma unroll
    for (int mt = 0; mt < 2; mt++) {
        #pragma unroll
        for (int nt = 0; nt < 4; nt++) {
            const int col = h32 + nt * 8 + 2 * tg;
            const long r1 = rowbase + qb + mt * 16 + gq;
            *(float2*)(g_qkv + r1 * QKVW + col) =
                make_float2(ftf(acc2[mt][nt][0]), ftf(acc2[mt][nt][1]));
            *(float2*)(g_qkv + (r1 + 8) * QKVW + col) =
                make_float2(ftf(acc2[mt][nt][2]), ftf(acc2[mt][nt][3]));
        }
    }
}

// ---------------------------------------------------------------------------
// Kernel C: proj (BN=128, grid-swapped, zero CVT).
// ---------------------------------------------------------------------------
#define PTS     36
#define PTILE_F (128 * PTS)
#define PBUF_F  (2 * PTILE_F)
#define SMEM_PROJ (2 * PBUF_F * 4)

__global__ __launch_bounds__(256) void proj_mma(
    const float* __restrict__ b_proj, float* __restrict__ out)
{
    extern __shared__ float sm[];
    const int tid = threadIdx.x;
    const long row0 = (long)blockIdx.y * 128;
    const int colb = blockIdx.x * 128;

    const int ldr = tid >> 1;
    const int ldc = (tid & 1) << 4;
    long row = row0 + ldr;
    int b = (int)(row >> 14);
    int n = (int)(row & 16383);
    int i = n >> 7, j = n & 127;
    int srcrow = ((b << 8) + (i >> 3) * 16 + (j >> 3)) * 64 + (i & 7) * 8 + (j & 7);
    const float* a_src0 = g_qkv + (long)srcrow * QKVW + ldc;
    const float* b_src0 = g_wproj + (long)(colb + ldr) * 256 + ldc;

    uint32_t smem_base = (uint32_t)__cvta_generic_to_shared(sm);
    uint32_t a_dst0 = smem_base + (uint32_t)(ldr * PTS + ldc) * 4;
    uint32_t b_dst0 = a_dst0 + PTILE_F * 4;

    const int lane = tid & 31, w = tid >> 5;
    const int wm = (w >> 1) * 32;
    const int wn = (w & 1) * 64;
    const int gq = lane >> 2, tg = lane & 3;

    float acc[2][8][4];
    #pragma unroll
    for (int mt = 0; mt < 2; mt++)
        #pragma unroll
        for (int nt = 0; nt < 8; nt++)
            #pragma unroll
            for (int q = 0; q < 4; q++) acc[mt][nt][q] = 0.f;

    {
        #pragma unroll
        for (int k = 0; k < 4; k++) CPA16(a_dst0 + k * 16, a_src0 + k * 4);
        #pragma unroll
        for (int k = 0; k < 4; k++) CPA16(b_dst0 + k * 16, b_src0 + k * 4);
        CP_COMMIT();
    }

    for (int kb = 0; kb < 8; ++kb) {
        CP_WAIT0();
        __syncthreads();
        if (kb < 7) {
            uint32_t off = (uint32_t)(((kb + 1) & 1) * PBUF_F * 4);
            const float* as = a_src0 + (kb + 1) * 32;
            const float* bs = b_src0 + (kb + 1) * 32;
            #pragma unroll
            for (int k = 0; k < 4; k++) CPA16(a_dst0 + off + k * 16, as + k * 4);
            #pragma unroll
            for (int k = 0; k < 4; k++) CPA16(b_dst0 + off + k * 16, bs + k * 4);
            CP_COMMIT();
        }
        const float* sA = sm + (kb & 1) * PBUF_F;
        const float* sB = sA + PTILE_F;

        #pragma unroll
        for (int ks = 0; ks < 4; ++ks) {
            const int k0 = ks * 8 + 2 * tg;
            uint32_t af[2][4];
            #pragma unroll
            for (int mt = 0; mt < 2; mt++) {
                const int r0 = wm + mt * 16;
                float2 lo = *(const float2*)&sA[(r0 + gq)     * PTS + k0];
                float2 hi = *(const float2*)&sA[(r0 + gq + 8) * PTS + k0];
                af[mt][0] = __float_as_uint(lo.x);
                af[mt][1] = __float_as_uint(hi.x);
                af[mt][2] = __float_as_uint(lo.y);
                af[mt][3] = __float_as_uint(hi.y);
            }
            #pragma unroll
            for (int nt = 0; nt < 8; nt++) {
                float2 bv = *(const float2*)&sB[(wn + nt * 8 + gq) * PTS + k0];
                uint32_t b0 = __float_as_uint(bv.x);
                uint32_t b1 = __float_as_uint(bv.y);
                mma_tf32(acc[0][nt], af[0][0], af[0][1], af[0][2], af[0][3], b0, b1);
                mma_tf32(acc[1][nt], af[1][0], af[1][1], af[1][2], af[1][3], b0, b1);
            }
        }
    }

    #pragma unroll
    for (int mt = 0; mt < 2; mt++) {
        #pragma unroll
        for (int nt = 0; nt < 8; nt++) {
            const int col = colb + wn + nt * 8 + tg * 2;
            const float2 bv = *(const float2*)(b_proj + col);
            const long r1 = row0 + wm + mt * 16 + gq;
            *(float2*)(out + r1 * NC + col) =
                make_float2(acc[mt][nt][0] + bv.x, acc[mt][nt][1] + bv.y);
            *(float2*)(out + (r1 + 8) * NC + col) =
                make_float2(acc[mt][nt][2] + bv.x, acc[mt][nt][3] + bv.y);
        }
    }
}

// ---------------------------------------------------------------------------
extern "C" void kernel_launch(void* const* d_in, const int* in_sizes, int n_in,
                              void* d_out, int out_size)
{
    const float* x      = (const float*)d_in[0];
    const float* query  = (const float*)d_in[1];
    const float* W_qk   = (const float*)d_in[2];
    const float* W_v    = (const float*)d_in[3];
    const float* W_proj = (const float*)d_in[4];
    const float* b_proj = (const float*)d_in[5];
    const float* W_pre  = (const float*)d_in[6];
    const float* W_post = (const float*)d_in[7];
    float* out = (float*)d_out;

    cudaFuncSetAttribute(qkv_mma, cudaFuncAttributeMaxDynamicSharedMemorySize, SMEM_G2);
    cudaFuncSetAttribute(attn_kernel, cudaFuncAttributeMaxDynamicSharedMemorySize, SMEM_ATTN_BYTES);
    cudaFuncSetAttribute(proj_mma, cudaFuncAttributeMaxDynamicSharedMemorySize, SMEM_PROJ);

    cvt_weights<<<128, 256>>>(W_qk, W_v, W_proj);
    qkv_mma<<<dim3(12, 1024), 256, SMEM_G2>>>(x, query);
    attn_kernel<<<NWIN * 2, 256, SMEM_ATTN_BYTES>>>(W_pre, W_post);
    proj_mma<<<dim3(2, 1024), 256, SMEM_PROJ>>>(b_proj, out);
}

// round 15
// speedup vs baseline: 1.3556x; 1.3073x over previous
#include <cuda_runtime.h>
#include <cuda_fp16.h>
#include <cstdint>

// Problem constants
#define NB    8
#define NTOK  16384
#define NC    256
#define NWIN  2048    // B * (16x16 windows)

// fp16 intermediates, NATURAL channel order (no permutation).
// g_qk: [win*64 tokens][512]  = Q(256) | K(256); attention O overwrites Q.
// g_v : [win][256 ch][64 tok] = V TRANSPOSED per window.
__device__ __half g_qk[(size_t)NWIN * 64 * 512];
__device__ __half g_v[(size_t)NWIN * 256 * 64];
__device__ __half g_w16qk[512 * 256];
__device__ __half g_w16v[256 * 256];
__device__ __half g_w16p[256 * 256];

// ---------------------------------------------------------------------------
__device__ __forceinline__ uint32_t f2tf(float f) {
    uint32_t u;
    asm("cvt.rna.tf32.f32 %0, %1;" : "=r"(u) : "f"(f));
    return u;
}
__device__ __forceinline__ float ftf(float f) {
    return __uint_as_float(f2tf(f));
}
__device__ __forceinline__ void mma_tf32(float c[4],
    uint32_t a0, uint32_t a1, uint32_t a2, uint32_t a3,
    uint32_t b0, uint32_t b1)
{
    asm volatile(
        "mma.sync.aligned.m16n8k8.row.col.f32.tf32.tf32.f32 "
        "{%0,%1,%2,%3},{%4,%5,%6,%7},{%8,%9},{%0,%1,%2,%3};"
        : "+f"(c[0]), "+f"(c[1]), "+f"(c[2]), "+f"(c[3])
        : "r"(a0), "r"(a1), "r"(a2), "r"(a3), "r"(b0), "r"(b1));
}
__device__ __forceinline__ void mma_f16(float c[4],
    uint32_t a0, uint32_t a1, uint32_t a2, uint32_t a3,
    uint32_t b0, uint32_t b1)
{
    asm volatile(
        "mma.sync.aligned.m16n8k16.row.col.f32.f16.f16.f32 "
        "{%0,%1,%2,%3},{%4,%5,%6,%7},{%8,%9},{%0,%1,%2,%3};"
        : "+f"(c[0]), "+f"(c[1]), "+f"(c[2]), "+f"(c[3])
        : "r"(a0), "r"(a1), "r"(a2), "r"(a3), "r"(b0), "r"(b1));
}
__device__ __forceinline__ uint32_t f22h(float lo, float hi) {
    __half2 h = __floats2half2_rn(lo, hi);
    return *(uint32_t*)&h;
}
#define CPA16(dst, src) \
    asm volatile("cp.async.cg.shared.global [%0],[%1],16;" :: "r"(dst), "l"(src))
#define CP_COMMIT() asm volatile("cp.async.commit_group;")
#define CP_WAIT0()  asm volatile("cp.async.wait_group 0;" ::: "memory")

// ---------------------------------------------------------------------------
// Weights: round to fp16 (natural order)
// ---------------------------------------------------------------------------
__global__ __launch_bounds__(256) void cvt_weights(
    const float* __restrict__ wqk, const float* __restrict__ wv,
    const float* __restrict__ wproj)
{
    const int t = blockIdx.x * 256 + threadIdx.x;
    const int off = t * 8;
    const float* s; __half* d;
    if (off < 131072)      { s = wqk + off;            d = g_w16qk + off; }
    else if (off < 196608) { s = wv + off - 131072;    d = g_w16v + off - 131072; }
    else                   { s = wproj + off - 196608; d = g_w16p + off - 196608; }
    float4 v0 = ((const float4*)s)[0], v1 = ((const float4*)s)[1];
    __half2 h0 = __floats2half2_rn(v0.x, v0.y);
    __half2 h1 = __floats2half2_rn(v0.z, v0.w);
    __half2 h2 = __floats2half2_rn(v1.x, v1.y);
    __half2 h3 = __floats2half2_rn(v1.z, v1.w);
    uint4 pack;
    pack.x = *(uint32_t*)&h0; pack.y = *(uint32_t*)&h1;
    pack.z = *(uint32_t*)&h2; pack.w = *(uint32_t*)&h3;
    *(uint4*)d = pack;
}

// ---------------------------------------------------------------------------
// Kernel A: Q|K|V GEMM, fp16 m16n8k16. BM=128, BN=64, BK=32, 8 warps 32x32.
// A staged fp32 (cvt at frag load); B fp16. Grid-swapped for L2 A-reuse.
// cb 0..7 -> Q|K cols cb*64 of g_qk; cb 8..11 -> V (written TRANSPOSED to g_v).
// ---------------------------------------------------------------------------
#define TSA 36                         // A stride (floats)
#define RSB 40                         // B stride (halves)
#define QKV_ABYTES (128 * TSA * 4)     // 18432
#define QKV_BBYTES (64 * RSB * 2)      // 5120
#define QKV_BUF (QKV_ABYTES + QKV_BBYTES)
#define SMEM_QKV (2 * QKV_BUF)         // 47104 -> 4 CTAs/SM

__global__ __launch_bounds__(256, 4) void qkv_mma(
    const float* __restrict__ x, const float* __restrict__ query)
{
    extern __shared__ char smc[];
    const int tid = threadIdx.x;
    const int cb  = blockIdx.x;     // 0..11
    const int p   = blockIdx.y;     // 0..1023

    const float* in = (cb < 8) ? query : x;
    const __half* Wt = (cb < 8) ? (g_w16qk + (long)cb * 64 * 256)
                                : (g_w16v  + (long)(cb - 8) * 64 * 256);

    const int ldrA = tid >> 1, ldcA = (tid & 1) << 4;   // 2 thr/row, 16 floats
    const int ldrB = tid >> 2, hB = (tid & 3) << 3;     // 4 thr/row, 8 halves
    int win = p * 2 + (ldrA >> 6);
    int s   = ldrA & 63;
    int b   = win >> 8, g = win & 255;
    int n   = ((g >> 4) * 8 + (s >> 3)) * 128 + (g & 15) * 8 + (s & 7);
    const float* a_src0 = in + ((long)b * NTOK + n) * 256 + ldcA;
    const __half* b_src0 = Wt + (long)ldrB * 256 + hB;

    uint32_t smem_base = (uint32_t)__cvta_generic_to_shared(smc);
    uint32_t a_dst0 = smem_base + (uint32_t)(ldrA * TSA + ldcA) * 4;
    uint32_t b_dst0 = smem_base + QKV_ABYTES + (uint32_t)(ldrB * RSB + hB) * 2;

    const int lane = tid & 31, w = tid >> 5;
    const int wm = (w >> 1) * 32;
    const int wn = (w & 1) * 32;
    const int gq = lane >> 2, tg = lane & 3;

    float acc[2][4][4];
    #pragma unroll
    for (int mt = 0; mt < 2; mt++)
        #pragma unroll
        for (int nt = 0; nt < 4; nt++)
            #pragma unroll
            for (int q = 0; q < 4; q++) acc[mt][nt][q] = 0.f;

    {
        #pragma unroll
        for (int i = 0; i < 4; i++) CPA16(a_dst0 + i * 16, a_src0 + i * 4);
        CPA16(b_dst0, b_src0);
        CP_COMMIT();
    }

    for (int kb = 0; kb < 8; ++kb) {
        CP_WAIT0();
        __syncthreads();
        if (kb < 7) {
            uint32_t off = (uint32_t)(((kb + 1) & 1) * QKV_BUF);
            const float* as = a_src0 + (kb + 1) * 32;
            const __half* bs = b_src0 + (kb + 1) * 32;
            #pragma unroll
            for (int i = 0; i < 4; i++) CPA16(a_dst0 + off + i * 16, as + i * 4);
            CPA16(b_dst0 + off, bs);
            CP_COMMIT();
        }
        const float* sA = (const float*)(smc + (kb & 1) * QKV_BUF);
        const __half* sB = (const __half*)(smc + (kb & 1) * QKV_BUF + QKV_ABYTES);

        #pragma unroll
        for (int ks = 0; ks < 2; ++ks) {
            const int k0 = ks * 16 + 2 * tg;
            uint32_t af[2][4];
            #pragma unroll
            for (int mt = 0; mt < 2; mt++) {
                const int r0 = wm + mt * 16;
                float2 p0 = *(const float2*)&sA[(r0 + gq)     * TSA + k0];
                float2 p1 = *(const float2*)&sA[(r0 + gq + 8) * TSA + k0];
                float2 p2 = *(const float2*)&sA[(r0 + gq)     * TSA + k0 + 8];
                float2 p3 = *(const float2*)&sA[(r0 + gq + 8) * TSA + k0 + 8];
                af[mt][0] = f22h(p0.x, p0.y);
                af[mt][1] = f22h(p1.x, p1.y);
                af[mt][2] = f22h(p2.x, p2.y);
                af[mt][3] = f22h(p3.x, p3.y);
            }
            #pragma unroll
            for (int nt = 0; nt < 4; nt++) {
                const int nb = wn + nt * 8 + gq;
                uint32_t b0 = *(const uint32_t*)&sB[nb * RSB + k0];
                uint32_t b1 = *(const uint32_t*)&sB[nb * RSB + k0 + 8];
                mma_f16(acc[0][nt], af[0][0], af[0][1], af[0][2], af[0][3], b0, b1);
                mma_f16(acc[1][nt], af[1][0], af[1][1], af[1][2], af[1][3], b0, b1);
            }
        }
    }

    const long row0 = (long)p * 128;
    if (cb < 8) {
        const int dstcol = cb * 64;
        #pragma unroll
        for (int mt = 0; mt < 2; mt++) {
            #pragma unroll
            for (int nt = 0; nt < 4; nt++) {
                const int ch = dstcol + wn + nt * 8 + 2 * tg;
                const long r1 = row0 + wm + mt * 16 + gq;
                *(__half2*)&g_qk[r1 * 512 + ch] =
                    __floats2half2_rn(acc[mt][nt][0], acc[mt][nt][1]);
                *(__half2*)&g_qk[(r1 + 8) * 512 + ch] =
                    __floats2half2_rn(acc[mt][nt][2], acc[mt][nt][3]);
            }
        }
    } else {
        const int vchb = (cb - 8) * 64;
        #pragma unroll
        for (int mt = 0; mt < 2; mt++) {
            #pragma unroll
            for (int nt = 0; nt < 4; nt++) {
                const int ch = vchb + wn + nt * 8 + 2 * tg;
                const long r1 = row0 + wm + mt * 16 + gq;
                const long w2 = r1 >> 6;
                const int tok = (int)(r1 & 63);
                __half* vb = g_v + (w2 * 256 + ch) * 64 + tok;
                vb[0]      = __float2half_rn(acc[mt][nt][0]);
                vb[64]     = __float2half_rn(acc[mt][nt][1]);   // ch+1
                vb[8]      = __float2half_rn(acc[mt][nt][2]);   // tok+8
                vb[72]     = __float2half_rn(acc[mt][nt][3]);   // ch+1, tok+8
            }
        }
    }
}

// ---------------------------------------------------------------------------
// Kernel B: attention, fp16 mma for scores and O. Block per (window, q-half),
// warp = head. Mixes/softmax on fp32 planes (tf32 mix-mma, as R14).
// ---------------------------------------------------------------------------
#define PL2 2120
#define RS  66
#define OFF_WPRE  (8 * PL2)
#define OFF_WPOST (OFF_WPRE + 64)
#define OFF_RSUM  (OFF_WPRE + 128)
#define SMEM_ATTN_BYTES ((OFF_RSUM + 256) * 4)

__global__ __launch_bounds__(256) void attn_kernel(
    const float* __restrict__ W_pre, const float* __restrict__ W_post)
{
    extern __shared__ float sm[];
    float* s_attn  = sm;
    float* s_wpre  = sm + OFF_WPRE;
    float* s_wpost = sm + OFF_WPOST;
    float* s_rsum  = sm + OFF_RSUM;

    const int tid  = threadIdx.x;
    const int lane = tid & 31;
    const int h    = tid >> 5;
    const int gq = lane >> 2, tg = lane & 3;
    const int h32 = h * 32;
    const int win = blockIdx.x >> 1;
    const int qb  = (blockIdx.x & 1) * 32;
    const long rowbase = (long)win * 64;
    const __half* qk = g_qk + rowbase * 512;

    if (tid < 64) { s_wpre[tid] = W_pre[tid]; s_wpost[tid] = W_post[tid]; }

    // ---- scores: S_h = Q_h @ K_h^T (M=32, N=64, K=32; 2 k16 steps) ----
    float acc[2][8][4];
    #pragma unroll
    for (int mt = 0; mt < 2; mt++)
        #pragma unroll
        for (int nt = 0; nt < 8; nt++)
            #pragma unroll
            for (int q = 0; q < 4; q++) acc[mt][nt][q] = 0.f;

    #pragma unroll
    for (int ks = 0; ks < 2; ++ks) {
        const int k0 = h32 + ks * 16 + 2 * tg;
        uint32_t a[2][4];
        #pragma unroll
        for (int mt = 0; mt < 2; mt++) {
            const int r0 = qb + mt * 16;
            a[mt][0] = *(const uint32_t*)&qk[(long)(r0 + gq)     * 512 + k0];
            a[mt][1] = *(const uint32_t*)&qk[(long)(r0 + gq + 8) * 512 + k0];
            a[mt][2] = *(const uint32_t*)&qk[(long)(r0 + gq)     * 512 + k0 + 8];
            a[mt][3] = *(const uint32_t*)&qk[(long)(r0 + gq + 8) * 512 + k0 + 8];
        }
        #pragma unroll
        for (int nt = 0; nt < 8; nt++) {
            const int nb = nt * 8 + gq;
            uint32_t b0 = *(const uint32_t*)&qk[(long)nb * 512 + 256 + k0];
            uint32_t b1 = *(const uint32_t*)&qk[(long)nb * 512 + 256 + k0 + 8];
            #pragma unroll
            for (int mt = 0; mt < 2; mt++)
                mma_f16(acc[mt][nt], a[mt][0], a[mt][1], a[mt][2], a[mt][3], b0, b1);
        }
    }

    // STS scaled + tf32-rounded scores (mix mma A needs no CVT)
    const float scale = 0.17677669529663687f;
    float* pl = s_attn + h * PL2;
    #pragma unroll
    for (int mt = 0; mt < 2; mt++) {
        #pragma unroll
        for (int nt = 0; nt < 8; nt++) {
            const int q0 = mt * 16 + gq, c = nt * 8 + 2 * tg;
            *(float2*)&pl[q0 * RS + c] =
                make_float2(ftf(acc[mt][nt][0] * scale), ftf(acc[mt][nt][1] * scale));
            *(float2*)&pl[(q0 + 8) * RS + c] =
                make_float2(ftf(acc[mt][nt][2] * scale), ftf(acc[mt][nt][3] * scale));
        }
    }
    __syncthreads();

    // ---- pre-mix (tensor tf32) + exp: warp h owns rows [h*256, h*256+256) ----
    {
        const uint32_t wb0 = f2tf(s_wpre[gq * 8 + tg]);
        const uint32_t wb1 = f2tf(s_wpre[gq * 8 + tg + 4]);
        #pragma unroll 4
        for (int i = 0; i < 16; ++i) {
            const int rb = h * 256 + i * 16;
            const int q = rb >> 6, kk = (rb & 63) + gq;
            uint32_t a0 = __float_as_uint(s_attn[tg * PL2 + q * RS + kk]);
            uint32_t a1 = __float_as_uint(s_attn[tg * PL2 + q * RS + kk + 8]);
            uint32_t a2 = __float_as_uint(s_attn[(tg + 4) * PL2 + q * RS + kk]);
            uint32_t a3 = __float_as_uint(s_attn[(tg + 4) * PL2 + q * RS + kk + 8]);
            float c[4] = {0.f, 0.f, 0.f, 0.f};
            mma_tf32(c, a0, a1, a2, a3, wb0, wb1);
            s_attn[(2 * tg)     * PL2 + q * RS + kk]     = __expf(c[0]);
            s_attn[(2 * tg + 1) * PL2 + q * RS + kk]     = __expf(c[1]);
            s_attn[(2 * tg)     * PL2 + q * RS + kk + 8] = __expf(c[2]);
            s_attn[(2 * tg + 1) * PL2 + q * RS + kk + 8] = __expf(c[3]);
        }
    }
    __syncthreads();

    // ---- softmax denominator ----
    {
        int q = tid >> 3, hh = tid & 7;
        float s = 0.f;
        #pragma unroll 8
        for (int k = 0; k < 64; k++) s += s_attn[hh * PL2 + q * RS + k];
        s_rsum[tid] = 1.0f / s;
    }
    __syncthreads();

    // ---- post-mix (tensor tf32) ----
    {
        const uint32_t wb0 = f2tf(s_wpost[gq * 8 + tg]);
        const uint32_t wb1 = f2tf(s_wpost[gq * 8 + tg + 4]);
        #pragma unroll 4
        for (int i = 0; i < 16; ++i) {
            const int rb = h * 256 + i * 16;
            const int q = rb >> 6, kk = (rb & 63) + gq;
            const float rs0 = s_rsum[q * 8 + tg];
            const float rs1 = s_rsum[q * 8 + tg + 4];
            uint32_t a0 = f2tf(s_attn[tg * PL2 + q * RS + kk] * rs0);
            uint32_t a1 = f2tf(s_attn[tg * PL2 + q * RS + kk + 8] * rs0);
            uint32_t a2 = f2tf(s_attn[(tg + 4) * PL2 + q * RS + kk] * rs1);
            uint32_t a3 = f2tf(s_attn[(tg + 4) * PL2 + q * RS + kk + 8] * rs1);
            float c[4] = {0.f, 0.f, 0.f, 0.f};
            mma_tf32(c, a0, a1, a2, a3, wb0, wb1);
            s_attn[(2 * tg)     * PL2 + q * RS + kk]     = c[0];
            s_attn[(2 * tg + 1) * PL2 + q * RS + kk]     = c[1];
            s_attn[(2 * tg)     * PL2 + q * RS + kk + 8] = c[2];
            s_attn[(2 * tg + 1) * PL2 + q * RS + kk + 8] = c[3];
        }
    }
    __syncthreads();

    // ---- O_h = A_h @ V_h (M=32, N=32, K=64; 4 k16 steps; V^T fp16) ----
    float acc2[2][4][4];
    #pragma unroll
    for (int mt = 0; mt < 2; mt++)
        #pragma unroll
        for (int nt = 0; nt < 4; nt++)
            #pragma unroll
            for (int q = 0; q < 4; q++) acc2[mt][nt][q] = 0.f;

    const __half* vt = g_v + (long)win * 256 * 64;
    #pragma unroll
    for (int ks = 0; ks < 4; ++ks) {
        const int k0 = ks * 16 + 2 * tg;
        uint32_t a[2][4];
        #pragma unroll
        for (int mt = 0; mt < 2; mt++) {
            const int r0 = mt * 16;
            float2 p0 = *(const float2*)&pl[(r0 + gq)     * RS + k0];
            float2 p1 = *(const float2*)&pl[(r0 + gq + 8) * RS + k0];
            float2 p2 = *(const float2*)&pl[(r0 + gq)     * RS + k0 + 8];
            float2 p3 = *(const float2*)&pl[(r0 + gq + 8) * RS + k0 + 8];
            a[mt][0] = f22h(p0.x, p0.y);
            a[mt][1] = f22h(p1.x, p1.y);
            a[mt][2] = f22h(p2.x, p2.y);
            a[mt][3] = f22h(p3.x, p3.y);
        }
        #pragma unroll
        for (int nt = 0; nt < 4; nt++) {
            const int ch = h32 + nt * 8 + gq;
            uint32_t b0 = *(const uint32_t*)&vt[(long)ch * 64 + k0];
            uint32_t b1 = *(const uint32_t*)&vt[(long)ch * 64 + k0 + 8];
            #pragma unroll
            for (int mt = 0; mt < 2; mt++)
                mma_f16(acc2[mt][nt], a[mt][0], a[mt][1], a[mt][2], a[mt][3], b0, b1);
        }
    }

    // O -> fp16, overwrite Q columns
    #pragma unroll
    for (int mt = 0; mt < 2; mt++) {
        #pragma unroll
        for (int nt = 0; nt < 4; nt++) {
            const int col = h32 + nt * 8 + 2 * tg;
            const long r1 = rowbase + qb + mt * 16 + gq;
            *(__half2*)&g_qk[r1 * 512 + col] =
                __floats2half2_rn(acc2[mt][nt][0], acc2[mt][nt][1]);
            *(__half2*)&g_qk[(r1 + 8) * 512 + col] =
                __floats2half2_rn(acc2[mt][nt][2], acc2[mt][nt][3]);
        }
    }
}

// ---------------------------------------------------------------------------
// Kernel C: proj, fp16 m16n8k16. BM=128, BN=128, BK=32. Zero CVT (A fp16).
// Grid-swapped for L2 reuse of the gathered A tile.
// ---------------------------------------------------------------------------
#define PRS 40                          // smem stride (halves) for A and B
#define P_TBYTES (128 * PRS * 2)        // 10240 per tile
#define P_BUF (2 * P_TBYTES)            // A + B
#define SMEM_PROJ (2 * P_BUF)           // 40960

__global__ __launch_bounds__(256) void proj_mma(
    const float* __restrict__ b_proj, float* __restrict__ out)
{
    extern __shared__ char smc[];
    const int tid = threadIdx.x;
    const long row0 = (long)blockIdx.y * 128;
    const int colb = blockIdx.x * 128;

    // loaders: thread covers rows (tid>>2) and (tid>>2)+64, 8 halves each
    const int ldr = tid >> 2, hoff = (tid & 3) << 3;
    long rA0 = row0 + ldr, rA1 = row0 + ldr + 64;
    int srcrow[2];
    {
        long rows[2] = { rA0, rA1 };
        #pragma unroll
        for (int u = 0; u < 2; u++) {
            int b = (int)(rows[u] >> 14);
            int n = (int)(rows[u] & 16383);
            int i = n >> 7, j = n & 127;
            srcrow[u] = ((b << 8) + (i >> 3) * 16 + (j >> 3)) * 64 + (i & 7) * 8 + (j & 7);
        }
    }
    const __half* a_src[2] = {
        g_qk + (long)srcrow[0] * 512 + hoff,
        g_qk + (long)srcrow[1] * 512 + hoff
    };
    const __half* b_src[2] = {
        g_w16p + (long)(colb + ldr) * 256 + hoff,
        g_w16p + (long)(colb + ldr + 64) * 256 + hoff
    };

    uint32_t smem_base = (uint32_t)__cvta_generic_to_shared(smc);
    uint32_t a_dst[2] = {
        smem_base + (uint32_t)(ldr * PRS + hoff) * 2,
        smem_base + (uint32_t)((ldr + 64) * PRS + hoff) * 2
    };
    uint32_t b_dst[2] = {
        smem_base + P_TBYTES + (uint32_t)(ldr * PRS + hoff) * 2,
        smem_base + P_TBYTES + (uint32_t)((ldr + 64) * PRS + hoff) * 2
    };

    const int lane = tid & 31, w = tid >> 5;
    const int wm = (w >> 1) * 32;
    const int wn = (w & 1) * 64;
    const int gq = lane >> 2, tg = lane & 3;

    float acc[2][8][4];
    #pragma unroll
    for (int mt = 0; mt < 2; mt++)
        #pragma unroll
        for (int nt = 0; nt < 8; nt++)
            #pragma unroll
            for (int q = 0; q < 4; q++) acc[mt][nt][q] = 0.f;

    {
        #pragma unroll
        for (int u = 0; u < 2; u++) { CPA16(a_dst[u], a_src[u]); CPA16(b_dst[u], b_src[u]); }
        CP_COMMIT();
    }

    for (int kb = 0; kb < 8; ++kb) {
        CP_WAIT0();
        __syncthreads();
        if (kb < 7) {
            uint32_t off = (uint32_t)(((kb + 1) & 1) * P_BUF);
            #pragma unroll
            for (int u = 0; u < 2; u++) {
                CPA16(a_dst[u] + off, a_src[u] + (kb + 1) * 32);
                CPA16(b_dst[u] + off, b_src[u] + (kb + 1) * 32);
            }
            CP_COMMIT();
        }
        const __half* sA = (const __half*)(smc + (kb & 1) * P_BUF);
        const __half* sB = (const __half*)(smc + (kb & 1) * P_BUF + P_TBYTES);

        #pragma unroll
        for (int ks = 0; ks < 2; ++ks) {
            const int k0 = ks * 16 + 2 * tg;
            uint32_t af[2][4];
            #pragma unroll
            for (int mt = 0; mt < 2; mt++) {
                const int r0 = wm + mt * 16;
                af[mt][0] = *(const uint32_t*)&sA[(r0 + gq)     * PRS + k0];
                af[mt][1] = *(const uint32_t*)&sA[(r0 + gq + 8) * PRS + k0];
                af[mt][2] = *(const uint32_t*)&sA[(r0 + gq)     * PRS + k0 + 8];
                af[mt][3] = *(const uint32_t*)&sA[(r0 + gq + 8) * PRS + k0 + 8];
            }
            #pragma unroll
            for (int nt = 0; nt < 8; nt++) {
                const int nb = wn + nt * 8 + gq;
                uint32_t b0 = *(const uint32_t*)&sB[nb * PRS + k0];
                uint32_t b1 = *(const uint32_t*)&sB[nb * PRS + k0 + 8];
                mma_f16(acc[0][nt], af[0][0], af[0][1], af[0][2], af[0][3], b0, b1);
                mma_f16(acc[1][nt], af[1][0], af[1][1], af[1][2], af[1][3], b0, b1);
            }
        }
    }

    #pragma unroll
    for (int mt = 0; mt < 2; mt++) {
        #pragma unroll
        for (int nt = 0; nt < 8; nt++) {
            const int col = colb + wn + nt * 8 + tg * 2;
            const float2 bv = *(const float2*)(b_proj + col);
            const long r1 = row0 + wm + mt * 16 + gq;
            *(float2*)(out + r1 * NC + col) =
                make_float2(acc[mt][nt][0] + bv.x, acc[mt][nt][1] + bv.y);
            *(float2*)(out + (r1 + 8) * NC + col) =
                make_float2(acc[mt][nt][2] + bv.x, acc[mt][nt][3] + bv.y);
        }
    }
}

// ---------------------------------------------------------------------------
extern "C" void kernel_launch(void* const* d_in, const int* in_sizes, int n_in,
                              void* d_out, int out_size)
{
    const float* x      = (const float*)d_in[0];
    const float* query  = (const float*)d_in[1];
    const float* W_qk   = (const float*)d_in[2];
    const float* W_v    = (const float*)d_in[3];
    const float* W_proj = (const float*)d_in[4];
    const float* b_proj = (const float*)d_in[5];
    const float* W_pre  = (const float*)d_in[6];
    const float* W_post = (const float*)d_in[7];
    float* out = (float*)d_out;

    cudaFuncSetAttribute(qkv_mma, cudaFuncAttributeMaxDynamicSharedMemorySize, SMEM_QKV);
    cudaFuncSetAttribute(attn_kernel, cudaFuncAttributeMaxDynamicSharedMemorySize, SMEM_ATTN_BYTES);
    cudaFuncSetAttribute(proj_mma, cudaFuncAttributeMaxDynamicSharedMemorySize, SMEM_PROJ);

    cvt_weights<<<128, 256>>>(W_qk, W_v, W_proj);
    qkv_mma<<<dim3(12, 1024), 256, SMEM_QKV>>>(x, query);
    attn_kernel<<<NWIN * 2, 256, SMEM_ATTN_BYTES>>>(W_pre, W_post);
    proj_mma<<<dim3(2, 1024), 256, SMEM_PROJ>>>(b_proj, out);
}

// round 16
// speedup vs baseline: 1.4037x; 1.0355x over previous
#include <cuda_runtime.h>
#include <cuda_fp16.h>
#include <cstdint>

// Problem constants
#define NB    8
#define NTOK  16384
#define NC    256
#define NWIN  2048    // B * (16x16 windows)

// fp16 intermediates, NATURAL channel order.
// g_qk: [win*64 tokens][512]  = Q(256) | K(256); attention O overwrites Q.
// g_v : [win][256 ch][64 tok] = V TRANSPOSED per window.
__device__ __half g_qk[(size_t)NWIN * 64 * 512];
__device__ __half g_v[(size_t)NWIN * 256 * 64];
__device__ __half g_w16qk[512 * 256];
__device__ __half g_w16v[256 * 256];
__device__ __half g_w16p[256 * 256];

// ---------------------------------------------------------------------------
__device__ __forceinline__ uint32_t f2tf(float f) {
    uint32_t u;
    asm("cvt.rna.tf32.f32 %0, %1;" : "=r"(u) : "f"(f));
    return u;
}
__device__ __forceinline__ float ftf(float f) {
    return __uint_as_float(f2tf(f));
}
__device__ __forceinline__ void mma_tf32(float c[4],
    uint32_t a0, uint32_t a1, uint32_t a2, uint32_t a3,
    uint32_t b0, uint32_t b1)
{
    asm volatile(
        "mma.sync.aligned.m16n8k8.row.col.f32.tf32.tf32.f32 "
        "{%0,%1,%2,%3},{%4,%5,%6,%7},{%8,%9},{%0,%1,%2,%3};"
        : "+f"(c[0]), "+f"(c[1]), "+f"(c[2]), "+f"(c[3])
        : "r"(a0), "r"(a1), "r"(a2), "r"(a3), "r"(b0), "r"(b1));
}
__device__ __forceinline__ void mma_f16(float c[4],
    uint32_t a0, uint32_t a1, uint32_t a2, uint32_t a3,
    uint32_t b0, uint32_t b1)
{
    asm volatile(
        "mma.sync.aligned.m16n8k16.row.col.f32.f16.f16.f32 "
        "{%0,%1,%2,%3},{%4,%5,%6,%7},{%8,%9},{%0,%1,%2,%3};"
        : "+f"(c[0]), "+f"(c[1]), "+f"(c[2]), "+f"(c[3])
        : "r"(a0), "r"(a1), "r"(a2), "r"(a3), "r"(b0), "r"(b1));
}
__device__ __forceinline__ uint32_t f22h(float lo, float hi) {
    __half2 h = __floats2half2_rn(lo, hi);
    return *(uint32_t*)&h;
}
#define LDMX4(r0, r1, r2, r3, addr) \
    asm volatile("ldmatrix.sync.aligned.m8n8.x4.shared.b16 {%0,%1,%2,%3}, [%4];" \
        : "=r"(r0), "=r"(r1), "=r"(r2), "=r"(r3) : "r"(addr))
#define CPA16(dst, src) \
    asm volatile("cp.async.cg.shared.global [%0],[%1],16;" :: "r"(dst), "l"(src))
#define CP_COMMIT() asm volatile("cp.async.commit_group;")
#define CP_WAIT0()  asm volatile("cp.async.wait_group 0;" ::: "memory")

// ---------------------------------------------------------------------------
// Weights: round to fp16 (natural order)
// ---------------------------------------------------------------------------
__global__ __launch_bounds__(256) void cvt_weights(
    const float* __restrict__ wqk, const float* __restrict__ wv,
    const float* __restrict__ wproj)
{
    const int t = blockIdx.x * 256 + threadIdx.x;
    const int off = t * 8;
    const float* s; __half* d;
    if (off < 131072)      { s = wqk + off;            d = g_w16qk + off; }
    else if (off < 196608) { s = wv + off - 131072;    d = g_w16v + off - 131072; }
    else                   { s = wproj + off - 196608; d = g_w16p + off - 196608; }
    float4 v0 = ((const float4*)s)[0], v1 = ((const float4*)s)[1];
    __half2 h0 = __floats2half2_rn(v0.x, v0.y);
    __half2 h1 = __floats2half2_rn(v0.z, v0.w);
    __half2 h2 = __floats2half2_rn(v1.x, v1.y);
    __half2 h3 = __floats2half2_rn(v1.z, v1.w);
    uint4 pack;
    pack.x = *(uint32_t*)&h0; pack.y = *(uint32_t*)&h1;
    pack.z = *(uint32_t*)&h2; pack.w = *(uint32_t*)&h3;
    *(uint4*)d = pack;
}

// ---------------------------------------------------------------------------
// Kernel A: Q|K|V GEMM, fp16 m16n8k16, B fragments via ldmatrix.x4.
// BM=128, BN=64, BK=32, 8 warps 32x32. Grid-swapped for L2 A-reuse.
// ---------------------------------------------------------------------------
#define TSA 36                         // A stride (floats)
#define RSB 40                         // B stride (halves)
#define QKV_ABYTES (128 * TSA * 4)     // 18432
#define QKV_BBYTES (64 * RSB * 2)      // 5120
#define QKV_BUF (QKV_ABYTES + QKV_BBYTES)
#define SMEM_QKV (2 * QKV_BUF)         // 47104 -> 4 CTAs/SM

__global__ __launch_bounds__(256, 4) void qkv_mma(
    const float* __restrict__ x, const float* __restrict__ query)
{
    extern __shared__ char smc[];
    const int tid = threadIdx.x;
    const int cb  = blockIdx.x;     // 0..11
    const int p   = blockIdx.y;     // 0..1023

    const float* in = (cb < 8) ? query : x;
    const __half* Wt = (cb < 8) ? (g_w16qk + (long)cb * 64 * 256)
                                : (g_w16v  + (long)(cb - 8) * 64 * 256);

    const int ldrA = tid >> 1, ldcA = (tid & 1) << 4;
    const int ldrB = tid >> 2, hB = (tid & 3) << 3;
    int win = p * 2 + (ldrA >> 6);
    int s   = ldrA & 63;
    int b   = win >> 8, g = win & 255;
    int n   = ((g >> 4) * 8 + (s >> 3)) * 128 + (g & 15) * 8 + (s & 7);
    const float* a_src0 = in + ((long)b * NTOK + n) * 256 + ldcA;
    const __half* b_src0 = Wt + (long)ldrB * 256 + hB;

    uint32_t smem_base = (uint32_t)__cvta_generic_to_shared(smc);
    uint32_t a_dst0 = smem_base + (uint32_t)(ldrA * TSA + ldcA) * 4;
    uint32_t b_dst0 = smem_base + QKV_ABYTES + (uint32_t)(ldrB * RSB + hB) * 2;

    const int lane = tid & 31, w = tid >> 5;
    const int wm = (w >> 1) * 32;
    const int wn = (w & 1) * 32;
    const int gq = lane >> 2, tg = lane & 3;

    // ldmatrix B lane offset: row = (lane&7) + (lane>>4)*8, khalf = (lane>>3)&1
    const uint32_t blm = (uint32_t)((((lane & 7) + ((lane >> 4) << 3)) * RSB
                                     + (((lane >> 3) & 1) << 3)) * 2);

    float acc[2][4][4];
    #pragma unroll
    for (int mt = 0; mt < 2; mt++)
        #pragma unroll
        for (int nt = 0; nt < 4; nt++)
            #pragma unroll
            for (int q = 0; q < 4; q++) acc[mt][nt][q] = 0.f;

    {
        #pragma unroll
        for (int i = 0; i < 4; i++) CPA16(a_dst0 + i * 16, a_src0 + i * 4);
        CPA16(b_dst0, b_src0);
        CP_COMMIT();
    }

    for (int kb = 0; kb < 8; ++kb) {
        CP_WAIT0();
        __syncthreads();
        if (kb < 7) {
            uint32_t off = (uint32_t)(((kb + 1) & 1) * QKV_BUF);
            const float* as = a_src0 + (kb + 1) * 32;
            const __half* bs = b_src0 + (kb + 1) * 32;
            #pragma unroll
            for (int i = 0; i < 4; i++) CPA16(a_dst0 + off + i * 16, as + i * 4);
            CPA16(b_dst0 + off, bs);
            CP_COMMIT();
        }
        const float* sA = (const float*)(smc + (kb & 1) * QKV_BUF);
        const uint32_t sB_u = smem_base + (uint32_t)((kb & 1) * QKV_BUF) + QKV_ABYTES + blm;

        #pragma unroll
        for (int ks = 0; ks < 2; ++ks) {
            const int k0 = ks * 16 + 2 * tg;
            uint32_t af[2][4];
            #pragma unroll
            for (int mt = 0; mt < 2; mt++) {
                const int r0 = wm + mt * 16;
                float2 p0 = *(const float2*)&sA[(r0 + gq)     * TSA + k0];
                float2 p1 = *(const float2*)&sA[(r0 + gq + 8) * TSA + k0];
                float2 p2 = *(const float2*)&sA[(r0 + gq)     * TSA + k0 + 8];
                float2 p3 = *(const float2*)&sA[(r0 + gq + 8) * TSA + k0 + 8];
                af[mt][0] = f22h(p0.x, p0.y);
                af[mt][1] = f22h(p1.x, p1.y);
                af[mt][2] = f22h(p2.x, p2.y);
                af[mt][3] = f22h(p3.x, p3.y);
            }
            // B frags for 4 nt via 2 ldmatrix.x4 (each covers 16 n-rows)
            uint32_t br[8];
            LDMX4(br[0], br[1], br[2], br[3],
                  sB_u + (uint32_t)((wn * RSB + ks * 16) * 2));
            LDMX4(br[4], br[5], br[6], br[7],
                  sB_u + (uint32_t)(((wn + 16) * RSB + ks * 16) * 2));
            #pragma unroll
            for (int nt = 0; nt < 4; nt++) {
                mma_f16(acc[0][nt], af[0][0], af[0][1], af[0][2], af[0][3],
                        br[2 * nt], br[2 * nt + 1]);
                mma_f16(acc[1][nt], af[1][0], af[1][1], af[1][2], af[1][3],
                        br[2 * nt], br[2 * nt + 1]);
            }
        }
    }

    const long row0 = (long)p * 128;
    if (cb < 8) {
        const int dstcol = cb * 64;
        #pragma unroll
        for (int mt = 0; mt < 2; mt++) {
            #pragma unroll
            for (int nt = 0; nt < 4; nt++) {
                const int ch = dstcol + wn + nt * 8 + 2 * tg;
                const long r1 = row0 + wm + mt * 16 + gq;
                *(__half2*)&g_qk[r1 * 512 + ch] =
                    __floats2half2_rn(acc[mt][nt][0], acc[mt][nt][1]);
                *(__half2*)&g_qk[(r1 + 8) * 512 + ch] =
                    __floats2half2_rn(acc[mt][nt][2], acc[mt][nt][3]);
            }
        }
    } else {
        const int vchb = (cb - 8) * 64;
        #pragma unroll
        for (int mt = 0; mt < 2; mt++) {
            #pragma unroll
            for (int nt = 0; nt < 4; nt++) {
                const int ch = vchb + wn + nt * 8 + 2 * tg;
                const long r1 = row0 + wm + mt * 16 + gq;
                const long w2 = r1 >> 6;
                const int tok = (int)(r1 & 63);
                __half* vb = g_v + (w2 * 256 + ch) * 64 + tok;
                vb[0]  = __float2half_rn(acc[mt][nt][0]);
                vb[64] = __float2half_rn(acc[mt][nt][1]);
                vb[8]  = __float2half_rn(acc[mt][nt][2]);
                vb[72] = __float2half_rn(acc[mt][nt][3]);
            }
        }
    }
}

// ---------------------------------------------------------------------------
// Kernel B: attention (R15 verbatim — fp16 scores/O mma, tf32 tensor mixes).
// ---------------------------------------------------------------------------
#define PL2 2120
#define RS  66
#define OFF_WPRE  (8 * PL2)
#define OFF_WPOST (OFF_WPRE + 64)
#define OFF_RSUM  (OFF_WPRE + 128)
#define SMEM_ATTN_BYTES ((OFF_RSUM + 256) * 4)

__global__ __launch_bounds__(256) void attn_kernel(
    const float* __restrict__ W_pre, const float* __restrict__ W_post)
{
    extern __shared__ float sm[];
    float* s_attn  = sm;
    float* s_wpre  = sm + OFF_WPRE;
    float* s_wpost = sm + OFF_WPOST;
    float* s_rsum  = sm + OFF_RSUM;

    const int tid  = threadIdx.x;
    const int lane = tid & 31;
    const int h    = tid >> 5;
    const int gq = lane >> 2, tg = lane & 3;
    const int h32 = h * 32;
    const int win = blockIdx.x >> 1;
    const int qb  = (blockIdx.x & 1) * 32;
    const long rowbase = (long)win * 64;
    const __half* qk = g_qk + rowbase * 512;

    if (tid < 64) { s_wpre[tid] = W_pre[tid]; s_wpost[tid] = W_post[tid]; }

    float acc[2][8][4];
    #pragma unroll
    for (int mt = 0; mt < 2; mt++)
        #pragma unroll
        for (int nt = 0; nt < 8; nt++)
            #pragma unroll
            for (int q = 0; q < 4; q++) acc[mt][nt][q] = 0.f;

    #pragma unroll
    for (int ks = 0; ks < 2; ++ks) {
        const int k0 = h32 + ks * 16 + 2 * tg;
        uint32_t a[2][4];
        #pragma unroll
        for (int mt = 0; mt < 2; mt++) {
            const int r0 = qb + mt * 16;
            a[mt][0] = *(const uint32_t*)&qk[(long)(r0 + gq)     * 512 + k0];
            a[mt][1] = *(const uint32_t*)&qk[(long)(r0 + gq + 8) * 512 + k0];
            a[mt][2] = *(const uint32_t*)&qk[(long)(r0 + gq)     * 512 + k0 + 8];
            a[mt][3] = *(const uint32_t*)&qk[(long)(r0 + gq + 8) * 512 + k0 + 8];
        }
        #pragma unroll
        for (int nt = 0; nt < 8; nt++) {
            const int nb = nt * 8 + gq;
            uint32_t b0 = *(const uint32_t*)&qk[(long)nb * 512 + 256 + k0];
            uint32_t b1 = *(const uint32_t*)&qk[(long)nb * 512 + 256 + k0 + 8];
            #pragma unroll
            for (int mt = 0; mt < 2; mt++)
                mma_f16(acc[mt][nt], a[mt][0], a[mt][1], a[mt][2], a[mt][3], b0, b1);
        }
    }

    const float scale = 0.17677669529663687f;
    float* pl = s_attn + h * PL2;
    #pragma unroll
    for (int mt = 0; mt < 2; mt++) {
        #pragma unroll
        for (int nt = 0; nt < 8; nt++) {
            const int q0 = mt * 16 + gq, c = nt * 8 + 2 * tg;
            *(float2*)&pl[q0 * RS + c] =
                make_float2(ftf(acc[mt][nt][0] * scale), ftf(acc[mt][nt][1] * scale));
            *(float2*)&pl[(q0 + 8) * RS + c] =
                make_float2(ftf(acc[mt][nt][2] * scale), ftf(acc[mt][nt][3] * scale));
        }
    }
    __syncthreads();

    {
        const uint32_t wb0 = f2tf(s_wpre[gq * 8 + tg]);
        const uint32_t wb1 = f2tf(s_wpre[gq * 8 + tg + 4]);
        #pragma unroll 4
        for (int i = 0; i < 16; ++i) {
            const int rb = h * 256 + i * 16;
            const int q = rb >> 6, kk = (rb & 63) + gq;
            uint32_t a0 = __float_as_uint(s_attn[tg * PL2 + q * RS + kk]);
            uint32_t a1 = __float_as_uint(s_attn[tg * PL2 + q * RS + kk + 8]);
            uint32_t a2 = __float_as_uint(s_attn[(tg + 4) * PL2 + q * RS + kk]);
            uint32_t a3 = __float_as_uint(s_attn[(tg + 4) * PL2 + q * RS + kk + 8]);
            float c[4] = {0.f, 0.f, 0.f, 0.f};
            mma_tf32(c, a0, a1, a2, a3, wb0, wb1);
            s_attn[(2 * tg)     * PL2 + q * RS + kk]     = __expf(c[0]);
            s_attn[(2 * tg + 1) * PL2 + q * RS + kk]     = __expf(c[1]);
            s_attn[(2 * tg)     * PL2 + q * RS + kk + 8] = __expf(c[2]);
            s_attn[(2 * tg + 1) * PL2 + q * RS + kk + 8] = __expf(c[3]);
        }
    }
    __syncthreads();

    {
        int q = tid >> 3, hh = tid & 7;
        float s = 0.f;
        #pragma unroll 8
        for (int k = 0; k < 64; k++) s += s_attn[hh * PL2 + q * RS + k];
        s_rsum[tid] = 1.0f / s;
    }
    __syncthreads();

    {
        const uint32_t wb0 = f2tf(s_wpost[gq * 8 + tg]);
        const uint32_t wb1 = f2tf(s_wpost[gq * 8 + tg + 4]);
        #pragma unroll 4
        for (int i = 0; i < 16; ++i) {
            const int rb = h * 256 + i * 16;
            const int q = rb >> 6, kk = (rb & 63) + gq;
            const float rs0 = s_rsum[q * 8 + tg];
            const float rs1 = s_rsum[q * 8 + tg + 4];
            uint32_t a0 = f2tf(s_attn[tg * PL2 + q * RS + kk] * rs0);
            uint32_t a1 = f2tf(s_attn[tg * PL2 + q * RS + kk + 8] * rs0);
            uint32_t a2 = f2tf(s_attn[(tg + 4) * PL2 + q * RS + kk] * rs1);
            uint32_t a3 = f2tf(s_attn[(tg + 4) * PL2 + q * RS + kk + 8] * rs1);
            float c[4] = {0.f, 0.f, 0.f, 0.f};
            mma_tf32(c, a0, a1, a2, a3, wb0, wb1);
            s_attn[(2 * tg)     * PL2 + q * RS + kk]     = c[0];
            s_attn[(2 * tg + 1) * PL2 + q * RS + kk]     = c[1];
            s_attn[(2 * tg)     * PL2 + q * RS + kk + 8] = c[2];
            s_attn[(2 * tg + 1) * PL2 + q * RS + kk + 8] = c[3];
        }
    }
    __syncthreads();

    float acc2[2][4][4];
    #pragma unroll
    for (int mt = 0; mt < 2; mt++)
        #pragma unroll
        for (int nt = 0; nt < 4; nt++)
            #pragma unroll
            for (int q = 0; q < 4; q++) acc2[mt][nt][q] = 0.f;

    const __half* vt = g_v + (long)win * 256 * 64;
    #pragma unroll
    for (int ks = 0; ks < 4; ++ks) {
        const int k0 = ks * 16 + 2 * tg;
        uint32_t a[2][4];
        #pragma unroll
        for (int mt = 0; mt < 2; mt++) {
            const int r0 = mt * 16;
            float2 p0 = *(const float2*)&pl[(r0 + gq)     * RS + k0];
            float2 p1 = *(const float2*)&pl[(r0 + gq + 8) * RS + k0];
            float2 p2 = *(const float2*)&pl[(r0 + gq)     * RS + k0 + 8];
            float2 p3 = *(const float2*)&pl[(r0 + gq + 8) * RS + k0 + 8];
            a[mt][0] = f22h(p0.x, p0.y);
            a[mt][1] = f22h(p1.x, p1.y);
            a[mt][2] = f22h(p2.x, p2.y);
            a[mt][3] = f22h(p3.x, p3.y);
        }
        #pragma unroll
        for (int nt = 0; nt < 4; nt++) {
            const int ch = h32 + nt * 8 + gq;
            uint32_t b0 = *(const uint32_t*)&vt[(long)ch * 64 + k0];
            uint32_t b1 = *(const uint32_t*)&vt[(long)ch * 64 + k0 + 8];
            #pragma unroll
            for (int mt = 0; mt < 2; mt++)
                mma_f16(acc2[mt][nt], a[mt][0], a[mt][1], a[mt][2], a[mt][3], b0, b1);
        }
    }

    #pragma unroll
    for (int mt = 0; mt < 2; mt++) {
        #pragma unroll
        for (int nt = 0; nt < 4; nt++) {
            const int col = h32 + nt * 8 + 2 * tg;
            const long r1 = rowbase + qb + mt * 16 + gq;
            *(__half2*)&g_qk[r1 * 512 + col] =
                __floats2half2_rn(acc2[mt][nt][0], acc2[mt][nt][1]);
            *(__half2*)&g_qk[(r1 + 8) * 512 + col] =
                __floats2half2_rn(acc2[mt][nt][2], acc2[mt][nt][3]);
        }
    }
}

// ---------------------------------------------------------------------------
// Kernel C: proj, fp16 m16n8k16, A and B fragments via ldmatrix.x4.
// BM=128, BN=128, BK=32. Grid-swapped for L2 reuse.
// ---------------------------------------------------------------------------
#define PRS 40
#define P_TBYTES (128 * PRS * 2)
#define P_BUF (2 * P_TBYTES)
#define SMEM_PROJ (2 * P_BUF)

__global__ __launch_bounds__(256) void proj_mma(
    const float* __restrict__ b_proj, float* __restrict__ out)
{
    extern __shared__ char smc[];
    const int tid = threadIdx.x;
    const long row0 = (long)blockIdx.y * 128;
    const int colb = blockIdx.x * 128;

    const int ldr = tid >> 2, hoff = (tid & 3) << 3;
    int srcrow[2];
    {
        long rows[2] = { row0 + ldr, row0 + ldr + 64 };
        #pragma unroll
        for (int u = 0; u < 2; u++) {
            int b = (int)(rows[u] >> 14);
            int n = (int)(rows[u] & 16383);
            int i = n >> 7, j = n & 127;
            srcrow[u] = ((b << 8) + (i >> 3) * 16 + (j >> 3)) * 64 + (i & 7) * 8 + (j & 7);
        }
    }
    const __half* a_src[2] = {
        g_qk + (long)srcrow[0] * 512 + hoff,
        g_qk + (long)srcrow[1] * 512 + hoff
    };
    const __half* b_src[2] = {
        g_w16p + (long)(colb + ldr) * 256 + hoff,
        g_w16p + (long)(colb + ldr + 64) * 256 + hoff
    };

    uint32_t smem_base = (uint32_t)__cvta_generic_to_shared(smc);
    uint32_t a_dst[2] = {
        smem_base + (uint32_t)(ldr * PRS + hoff) * 2,
        smem_base + (uint32_t)((ldr + 64) * PRS + hoff) * 2
    };
    uint32_t b_dst[2] = {
        smem_base + P_TBYTES + (uint32_t)(ldr * PRS + hoff) * 2,
        smem_base + P_TBYTES + (uint32_t)((ldr + 64) * PRS + hoff) * 2
    };

    const int lane = tid & 31, w = tid >> 5;
    const int wm = (w >> 1) * 32;
    const int wn = (w & 1) * 64;
    const int gq = lane >> 2, tg = lane & 3;

    // ldmatrix lane offsets (bytes):
    // A: row = (lane&7) + ((lane>>3)&1)*8, khalf = (lane>>4)
    const uint32_t alm = (uint32_t)(((((lane & 7) + (((lane >> 3) & 1) << 3)) * PRS)
                                     + ((lane >> 4) << 3)) * 2);
    // B: row = (lane&7) + (lane>>4)*8, khalf = (lane>>3)&1
    const uint32_t blm = (uint32_t)(((((lane & 7) + ((lane >> 4) << 3)) * PRS)
                                     + (((lane >> 3) & 1) << 3)) * 2);

    float acc[2][8][4];
    #pragma unroll
    for (int mt = 0; mt < 2; mt++)
        #pragma unroll
        for (int nt = 0; nt < 8; nt++)
            #pragma unroll
            for (int q = 0; q < 4; q++) acc[mt][nt][q] = 0.f;

    {
        #pragma unroll
        for (int u = 0; u < 2; u++) { CPA16(a_dst[u], a_src[u]); CPA16(b_dst[u], b_src[u]); }
        CP_COMMIT();
    }

    for (int kb = 0; kb < 8; ++kb) {
        CP_WAIT0();
        __syncthreads();
        if (kb < 7) {
            uint32_t off = (uint32_t)(((kb + 1) & 1) * P_BUF);
            #pragma unroll
            for (int u = 0; u < 2; u++) {
                CPA16(a_dst[u] + off, a_src[u] + (kb + 1) * 32);
                CPA16(b_dst[u] + off, b_src[u] + (kb + 1) * 32);
            }
            CP_COMMIT();
        }
        const uint32_t sA_u = smem_base + (uint32_t)((kb & 1) * P_BUF) + alm;
        const uint32_t sB_u = smem_base + (uint32_t)((kb & 1) * P_BUF) + P_TBYTES + blm;

        #pragma unroll
        for (int ks = 0; ks < 2; ++ks) {
            uint32_t af[2][4];
            #pragma unroll
            for (int mt = 0; mt < 2; mt++)
                LDMX4(af[mt][0], af[mt][1], af[mt][2], af[mt][3],
                      sA_u + (uint32_t)((((wm + mt * 16) * PRS) + ks * 16) * 2));
            uint32_t br[16];
            #pragma unroll
            for (int np = 0; np < 4; np++)
                LDMX4(br[4 * np], br[4 * np + 1], br[4 * np + 2], br[4 * np + 3],
                      sB_u + (uint32_t)((((wn + np * 16) * PRS) + ks * 16) * 2));
            #pragma unroll
            for (int nt = 0; nt < 8; nt++) {
                uint32_t b0 = br[2 * nt], b1 = br[2 * nt + 1];
                mma_f16(acc[0][nt], af[0][0], af[0][1], af[0][2], af[0][3], b0, b1);
                mma_f16(acc[1][nt], af[1][0], af[1][1], af[1][2], af[1][3], b0, b1);
            }
        }
    }

    #pragma unroll
    for (int mt = 0; mt < 2; mt++) {
        #pragma unroll
        for (int nt = 0; nt < 8; nt++) {
            const int col = colb + wn + nt * 8 + tg * 2;
            const float2 bv = *(const float2*)(b_proj + col);
            const long r1 = row0 + wm + mt * 16 + gq;
            *(float2*)(out + r1 * NC + col) =
                make_float2(acc[mt][nt][0] + bv.x, acc[mt][nt][1] + bv.y);
            *(float2*)(out + (r1 + 8) * NC + col) =
                make_float2(acc[mt][nt][2] + bv.x, acc[mt][nt][3] + bv.y);
        }
    }
}

// ---------------------------------------------------------------------------
extern "C" void kernel_launch(void* const* d_in, const int* in_sizes, int n_in,
                              void* d_out, int out_size)
{
    const float* x      = (const float*)d_in[0];
    const float* query  = (const float*)d_in[1];
    const float* W_qk   = (const float*)d_in[2];
    const float* W_v    = (const float*)d_in[3];
    const float* W_proj = (const float*)d_in[4];
    const float* b_proj = (const float*)d_in[5];
    const float* W_pre  = (const float*)d_in[6];
    const float* W_post = (const float*)d_in[7];
    float* out = (float*)d_out;

    cudaFuncSetAttribute(qkv_mma, cudaFuncAttributeMaxDynamicSharedMemorySize, SMEM_QKV);
    cudaFuncSetAttribute(attn_kernel, cudaFuncAttributeMaxDynamicSharedMemorySize, SMEM_ATTN_BYTES);
    cudaFuncSetAttribute(proj_mma, cudaFuncAttributeMaxDynamicSharedMemorySize, SMEM_PROJ);

    cvt_weights<<<128, 256>>>(W_qk, W_v, W_proj);
    qkv_mma<<<dim3(12, 1024), 256, SMEM_QKV>>>(x, query);
    attn_kernel<<<NWIN * 2, 256, SMEM_ATTN_BYTES>>>(W_pre, W_post);
    proj_mma<<<dim3(2, 1024), 256, SMEM_PROJ>>>(b_proj, out);
}

// round 17
// speedup vs baseline: 1.4087x; 1.0035x over previous
#include <cuda_runtime.h>
#include <cuda_fp16.h>
#include <cstdint>

// Problem constants
#define NB    8
#define NTOK  16384
#define NC    256
#define NWIN  2048    // B * (16x16 windows)

// fp16 intermediates, NATURAL channel order.
// g_qk: [win*64 tokens][512]  = Q(256, PRE-SCALED by d^-0.5) | K(256).
// g_v : [win][256 ch][64 tok] = V TRANSPOSED per window.
__device__ __half g_qk[(size_t)NWIN * 64 * 512];
__device__ __half g_v[(size_t)NWIN * 256 * 64];
__device__ __half g_w16qk[512 * 256];
__device__ __half g_w16v[256 * 256];
__device__ __half g_w16p[256 * 256];

// ---------------------------------------------------------------------------
__device__ __forceinline__ uint32_t f2tf(float f) {
    uint32_t u;
    asm("cvt.rna.tf32.f32 %0, %1;" : "=r"(u) : "f"(f));
    return u;
}
__device__ __forceinline__ float ftf(float f) {
    return __uint_as_float(f2tf(f));
}
__device__ __forceinline__ void mma_tf32(float c[4],
    uint32_t a0, uint32_t a1, uint32_t a2, uint32_t a3,
    uint32_t b0, uint32_t b1)
{
    asm volatile(
        "mma.sync.aligned.m16n8k8.row.col.f32.tf32.tf32.f32 "
        "{%0,%1,%2,%3},{%4,%5,%6,%7},{%8,%9},{%0,%1,%2,%3};"
        : "+f"(c[0]), "+f"(c[1]), "+f"(c[2]), "+f"(c[3])
        : "r"(a0), "r"(a1), "r"(a2), "r"(a3), "r"(b0), "r"(b1));
}
__device__ __forceinline__ void mma_f16(float c[4],
    uint32_t a0, uint32_t a1, uint32_t a2, uint32_t a3,
    uint32_t b0, uint32_t b1)
{
    asm volatile(
        "mma.sync.aligned.m16n8k16.row.col.f32.f16.f16.f32 "
        "{%0,%1,%2,%3},{%4,%5,%6,%7},{%8,%9},{%0,%1,%2,%3};"
        : "+f"(c[0]), "+f"(c[1]), "+f"(c[2]), "+f"(c[3])
        : "r"(a0), "r"(a1), "r"(a2), "r"(a3), "r"(b0), "r"(b1));
}
__device__ __forceinline__ uint32_t f22h(float lo, float hi) {
    __half2 h = __floats2half2_rn(lo, hi);
    return *(uint32_t*)&h;
}
#define LDMX4(r0, r1, r2, r3, addr) \
    asm volatile("ldmatrix.sync.aligned.m8n8.x4.shared.b16 {%0,%1,%2,%3}, [%4];" \
        : "=r"(r0), "=r"(r1), "=r"(r2), "=r"(r3) : "r"(addr))
#define CPA16(dst, src) \
    asm volatile("cp.async.cg.shared.global [%0],[%1],16;" :: "r"(dst), "l"(src))
#define CP_COMMIT() asm volatile("cp.async.commit_group;")
#define CP_WAIT0()  asm volatile("cp.async.wait_group 0;" ::: "memory")

// ---------------------------------------------------------------------------
// Weights: round to fp16 (natural order)
// ---------------------------------------------------------------------------
__global__ __launch_bounds__(256) void cvt_weights(
    const float* __restrict__ wqk, const float* __restrict__ wv,
    const float* __restrict__ wproj)
{
    const int t = blockIdx.x * 256 + threadIdx.x;
    const int off = t * 8;
    const float* s; __half* d;
    if (off < 131072)      { s = wqk + off;            d = g_w16qk + off; }
    else if (off < 196608) { s = wv + off - 131072;    d = g_w16v + off - 131072; }
    else                   { s = wproj + off - 196608; d = g_w16p + off - 196608; }
    float4 v0 = ((const float4*)s)[0], v1 = ((const float4*)s)[1];
    __half2 h0 = __floats2half2_rn(v0.x, v0.y);
    __half2 h1 = __floats2half2_rn(v0.z, v0.w);
    __half2 h2 = __floats2half2_rn(v1.x, v1.y);
    __half2 h3 = __floats2half2_rn(v1.z, v1.w);
    uint4 pack;
    pack.x = *(uint32_t*)&h0; pack.y = *(uint32_t*)&h1;
    pack.z = *(uint32_t*)&h2; pack.w = *(uint32_t*)&h3;
    *(uint4*)d = pack;
}

// ---------------------------------------------------------------------------
// Kernel A: Q|K|V GEMM, fp16 m16n8k16, B via ldmatrix.x4. Q pre-scaled.
// ---------------------------------------------------------------------------
#define TSA 36
#define RSB 40
#define QKV_ABYTES (128 * TSA * 4)
#define QKV_BBYTES (64 * RSB * 2)
#define QKV_BUF (QKV_ABYTES + QKV_BBYTES)
#define SMEM_QKV (2 * QKV_BUF)

__global__ __launch_bounds__(256, 4) void qkv_mma(
    const float* __restrict__ x, const float* __restrict__ query)
{
    extern __shared__ char smc[];
    const int tid = threadIdx.x;
    const int cb  = blockIdx.x;     // 0..11
    const int p   = blockIdx.y;     // 0..1023

    const float* in = (cb < 8) ? query : x;
    const __half* Wt = (cb < 8) ? (g_w16qk + (long)cb * 64 * 256)
                                : (g_w16v  + (long)(cb - 8) * 64 * 256);

    const int ldrA = tid >> 1, ldcA = (tid & 1) << 4;
    const int ldrB = tid >> 2, hB = (tid & 3) << 3;
    int win = p * 2 + (ldrA >> 6);
    int s   = ldrA & 63;
    int b   = win >> 8, g = win & 255;
    int n   = ((g >> 4) * 8 + (s >> 3)) * 128 + (g & 15) * 8 + (s & 7);
    const float* a_src0 = in + ((long)b * NTOK + n) * 256 + ldcA;
    const __half* b_src0 = Wt + (long)ldrB * 256 + hB;

    uint32_t smem_base = (uint32_t)__cvta_generic_to_shared(smc);
    uint32_t a_dst0 = smem_base + (uint32_t)(ldrA * TSA + ldcA) * 4;
    uint32_t b_dst0 = smem_base + QKV_ABYTES + (uint32_t)(ldrB * RSB + hB) * 2;

    const int lane = tid & 31, w = tid >> 5;
    const int wm = (w >> 1) * 32;
    const int wn = (w & 1) * 32;
    const int gq = lane >> 2, tg = lane & 3;

    const uint32_t blm = (uint32_t)((((lane & 7) + ((lane >> 4) << 3)) * RSB
                                     + (((lane >> 3) & 1) << 3)) * 2);

    float acc[2][4][4];
    #pragma unroll
    for (int mt = 0; mt < 2; mt++)
        #pragma unroll
        for (int nt = 0; nt < 4; nt++)
            #pragma unroll
            for (int q = 0; q < 4; q++) acc[mt][nt][q] = 0.f;

    {
        #pragma unroll
        for (int i = 0; i < 4; i++) CPA16(a_dst0 + i * 16, a_src0 + i * 4);
        CPA16(b_dst0, b_src0);
        CP_COMMIT();
    }

    for (int kb = 0; kb < 8; ++kb) {
        CP_WAIT0();
        __syncthreads();
        if (kb < 7) {
            uint32_t off = (uint32_t)(((kb + 1) & 1) * QKV_BUF);
            const float* as = a_src0 + (kb + 1) * 32;
            const __half* bs = b_src0 + (kb + 1) * 32;
            #pragma unroll
            for (int i = 0; i < 4; i++) CPA16(a_dst0 + off + i * 16, as + i * 4);
            CPA16(b_dst0 + off, bs);
            CP_COMMIT();
        }
        const float* sA = (const float*)(smc + (kb & 1) * QKV_BUF);
        const uint32_t sB_u = smem_base + (uint32_t)((kb & 1) * QKV_BUF) + QKV_ABYTES + blm;

        #pragma unroll
        for (int ks = 0; ks < 2; ++ks) {
            const int k0 = ks * 16 + 2 * tg;
            uint32_t af[2][4];
            #pragma unroll
            for (int mt = 0; mt < 2; mt++) {
                const int r0 = wm + mt * 16;
                float2 p0 = *(const float2*)&sA[(r0 + gq)     * TSA + k0];
                float2 p1 = *(const float2*)&sA[(r0 + gq + 8) * TSA + k0];
                float2 p2 = *(const float2*)&sA[(r0 + gq)     * TSA + k0 + 8];
                float2 p3 = *(const float2*)&sA[(r0 + gq + 8) * TSA + k0 + 8];
                af[mt][0] = f22h(p0.x, p0.y);
                af[mt][1] = f22h(p1.x, p1.y);
                af[mt][2] = f22h(p2.x, p2.y);
                af[mt][3] = f22h(p3.x, p3.y);
            }
            uint32_t br[8];
            LDMX4(br[0], br[1], br[2], br[3],
                  sB_u + (uint32_t)((wn * RSB + ks * 16) * 2));
            LDMX4(br[4], br[5], br[6], br[7],
                  sB_u + (uint32_t)(((wn + 16) * RSB + ks * 16) * 2));
            #pragma unroll
            for (int nt = 0; nt < 4; nt++) {
                mma_f16(acc[0][nt], af[0][0], af[0][1], af[0][2], af[0][3],
                        br[2 * nt], br[2 * nt + 1]);
                mma_f16(acc[1][nt], af[1][0], af[1][1], af[1][2], af[1][3],
                        br[2 * nt], br[2 * nt + 1]);
            }
        }
    }

    const long row0 = (long)p * 128;
    if (cb < 8) {
        // pre-scale Q (cb<4) by d^-0.5; K (cb>=4) unscaled
        const float osc = (cb < 4) ? 0.17677669529663687f : 1.0f;
        const int dstcol = cb * 64;
        #pragma unroll
        for (int mt = 0; mt < 2; mt++) {
            #pragma unroll
            for (int nt = 0; nt < 4; nt++) {
                const int ch = dstcol + wn + nt * 8 + 2 * tg;
                const long r1 = row0 + wm + mt * 16 + gq;
                *(__half2*)&g_qk[r1 * 512 + ch] =
                    __floats2half2_rn(acc[mt][nt][0] * osc, acc[mt][nt][1] * osc);
                *(__half2*)&g_qk[(r1 + 8) * 512 + ch] =
                    __floats2half2_rn(acc[mt][nt][2] * osc, acc[mt][nt][3] * osc);
            }
        }
    } else {
        const int vchb = (cb - 8) * 64;
        #pragma unroll
        for (int mt = 0; mt < 2; mt++) {
            #pragma unroll
            for (int nt = 0; nt < 4; nt++) {
                const int ch = vchb + wn + nt * 8 + 2 * tg;
                const long r1 = row0 + wm + mt * 16 + gq;
                const long w2 = r1 >> 6;
                const int tok = (int)(r1 & 63);
                __half* vb = g_v + (w2 * 256 + ch) * 64 + tok;
                vb[0]  = __float2half_rn(acc[mt][nt][0]);
                vb[64] = __float2half_rn(acc[mt][nt][1]);
                vb[8]  = __float2half_rn(acc[mt][nt][2]);
                vb[72] = __float2half_rn(acc[mt][nt][3]);
            }
        }
    }
}

// ---------------------------------------------------------------------------
// Kernel B: attention. 2 barriers only: rsum fused into pre-mix registers
// (warp h owns all k for q in [4h, 4h+4) -> warp-private reduction).
// ---------------------------------------------------------------------------
#define PL2 2120
#define RS  66
#define OFF_WPRE  (8 * PL2)
#define OFF_WPOST (OFF_WPRE + 64)
#define OFF_RSUM  (OFF_WPRE + 128)
#define SMEM_ATTN_BYTES ((OFF_RSUM + 256) * 4)

__global__ __launch_bounds__(256) void attn_kernel(
    const float* __restrict__ W_pre, const float* __restrict__ W_post)
{
    extern __shared__ float sm[];
    float* s_attn  = sm;
    float* s_wpre  = sm + OFF_WPRE;
    float* s_wpost = sm + OFF_WPOST;
    float* s_rsum  = sm + OFF_RSUM;

    const int tid  = threadIdx.x;
    const int lane = tid & 31;
    const int h    = tid >> 5;
    const int gq = lane >> 2, tg = lane & 3;
    const int h32 = h * 32;
    const int win = blockIdx.x >> 1;
    const int qb  = (blockIdx.x & 1) * 32;
    const long rowbase = (long)win * 64;
    const __half* qk = g_qk + rowbase * 512;

    if (tid < 64) { s_wpre[tid] = W_pre[tid]; s_wpost[tid] = W_post[tid]; }

    // ---- scores: S_h = Qs_h @ K_h^T (Q pre-scaled) ----
    float acc[2][8][4];
    #pragma unroll
    for (int mt = 0; mt < 2; mt++)
        #pragma unroll
        for (int nt = 0; nt < 8; nt++)
            #pragma unroll
            for (int q = 0; q < 4; q++) acc[mt][nt][q] = 0.f;

    #pragma unroll
    for (int ks = 0; ks < 2; ++ks) {
        const int k0 = h32 + ks * 16 + 2 * tg;
        uint32_t a[2][4];
        #pragma unroll
        for (int mt = 0; mt < 2; mt++) {
            const int r0 = qb + mt * 16;
            a[mt][0] = *(const uint32_t*)&qk[(long)(r0 + gq)     * 512 + k0];
            a[mt][1] = *(const uint32_t*)&qk[(long)(r0 + gq + 8) * 512 + k0];
            a[mt][2] = *(const uint32_t*)&qk[(long)(r0 + gq)     * 512 + k0 + 8];
            a[mt][3] = *(const uint32_t*)&qk[(long)(r0 + gq + 8) * 512 + k0 + 8];
        }
        #pragma unroll
        for (int nt = 0; nt < 8; nt++) {
            const int nb = nt * 8 + gq;
            uint32_t b0 = *(const uint32_t*)&qk[(long)nb * 512 + 256 + k0];
            uint32_t b1 = *(const uint32_t*)&qk[(long)nb * 512 + 256 + k0 + 8];
            #pragma unroll
            for (int mt = 0; mt < 2; mt++)
                mma_f16(acc[mt][nt], a[mt][0], a[mt][1], a[mt][2], a[mt][3], b0, b1);
        }
    }

    // STS tf32-rounded scores into plane h
    float* pl = s_attn + h * PL2;
    #pragma unroll
    for (int mt = 0; mt < 2; mt++) {
        #pragma unroll
        for (int nt = 0; nt < 8; nt++) {
            const int q0 = mt * 16 + gq, c = nt * 8 + 2 * tg;
            *(float2*)&pl[q0 * RS + c] =
                make_float2(ftf(acc[mt][nt][0]), ftf(acc[mt][nt][1]));
            *(float2*)&pl[(q0 + 8) * RS + c] =
                make_float2(ftf(acc[mt][nt][2]), ftf(acc[mt][nt][3]));
        }
    }
    __syncthreads();   // barrier 1: all score planes ready

    // ---- pre-mix (tensor tf32) + exp + FUSED row-sum accumulation ----
    {
        const uint32_t wb0 = f2tf(s_wpre[gq * 8 + tg]);
        const uint32_t wb1 = f2tf(s_wpre[gq * 8 + tg + 4]);
        float qsum[4][2];
        #pragma unroll
        for (int j = 0; j < 4; j++) { qsum[j][0] = 0.f; qsum[j][1] = 0.f; }

        #pragma unroll 4
        for (int i = 0; i < 16; ++i) {
            const int rb = h * 256 + i * 16;
            const int q = rb >> 6, kk = (rb & 63) + gq;
            uint32_t a0 = __float_as_uint(s_attn[tg * PL2 + q * RS + kk]);
            uint32_t a1 = __float_as_uint(s_attn[tg * PL2 + q * RS + kk + 8]);
            uint32_t a2 = __float_as_uint(s_attn[(tg + 4) * PL2 + q * RS + kk]);
            uint32_t a3 = __float_as_uint(s_attn[(tg + 4) * PL2 + q * RS + kk + 8]);
            float c[4] = {0.f, 0.f, 0.f, 0.f};
            mma_tf32(c, a0, a1, a2, a3, wb0, wb1);
            float e0 = __expf(c[0]), e1 = __expf(c[1]);
            float e2 = __expf(c[2]), e3 = __expf(c[3]);
            s_attn[(2 * tg)     * PL2 + q * RS + kk]     = e0;
            s_attn[(2 * tg + 1) * PL2 + q * RS + kk]     = e1;
            s_attn[(2 * tg)     * PL2 + q * RS + kk + 8] = e2;
            s_attn[(2 * tg + 1) * PL2 + q * RS + kk + 8] = e3;
            qsum[i >> 2][0] += e0 + e2;
            qsum[i >> 2][1] += e1 + e3;
        }
        // warp-private reduction over gq lanes (lane bits 2..4)
        #pragma unroll
        for (int j = 0; j < 4; ++j) {
            float s0 = qsum[j][0], s1 = qsum[j][1];
            #pragma unroll
            for (int m = 4; m <= 16; m <<= 1) {
                s0 += __shfl_xor_sync(0xffffffffu, s0, m);
                s1 += __shfl_xor_sync(0xffffffffu, s1, m);
            }
            if (gq == 0) {
                const int q = h * 4 + j;
                s_rsum[q * 8 + 2 * tg]     = 1.0f / s0;
                s_rsum[q * 8 + 2 * tg + 1] = 1.0f / s1;
            }
        }
        __syncwarp();
    }

    // ---- post-mix (tensor tf32): same warp-private q-range, no barrier ----
    {
        const uint32_t wb0 = f2tf(s_wpost[gq * 8 + tg]);
        const uint32_t wb1 = f2tf(s_wpost[gq * 8 + tg + 4]);
        #pragma unroll 4
        for (int i = 0; i < 16; ++i) {
            const int rb = h * 256 + i * 16;
            const int q = rb >> 6, kk = (rb & 63) + gq;
            const float rs0 = s_rsum[q * 8 + tg];
            const float rs1 = s_rsum[q * 8 + tg + 4];
            uint32_t a0 = f2tf(s_attn[tg * PL2 + q * RS + kk] * rs0);
            uint32_t a1 = f2tf(s_attn[tg * PL2 + q * RS + kk + 8] * rs0);
            uint32_t a2 = f2tf(s_attn[(tg + 4) * PL2 + q * RS + kk] * rs1);
            uint32_t a3 = f2tf(s_attn[(tg + 4) * PL2 + q * RS + kk + 8] * rs1);
            float c[4] = {0.f, 0.f, 0.f, 0.f};
            mma_tf32(c, a0, a1, a2, a3, wb0, wb1);
            s_attn[(2 * tg)     * PL2 + q * RS + kk]     = c[0];
            s_attn[(2 * tg + 1) * PL2 + q * RS + kk]     = c[1];
            s_attn[(2 * tg)     * PL2 + q * RS + kk + 8] = c[2];
            s_attn[(2 * tg + 1) * PL2 + q * RS + kk + 8] = c[3];
        }
    }
    __syncthreads();   // barrier 2: all mixed planes ready for O-mma

    // ---- O_h = A_h @ V_h (V^T fp16 via direct LDG) ----
    float acc2[2][4][4];
    #pragma unroll
    for (int mt = 0; mt < 2; mt++)
        #pragma unroll
        for (int nt = 0; nt < 4; nt++)
            #pragma unroll
            for (int q = 0; q < 4; q++) acc2[mt][nt][q] = 0.f;

    const __half* vt = g_v + (long)win * 256 * 64;
    #pragma unroll
    for (int ks = 0; ks < 4; ++ks) {
        const int k0 = ks * 16 + 2 * tg;
        uint32_t a[2][4];
        #pragma unroll
        for (int mt = 0; mt < 2; mt++) {
            const int r0 = mt * 16;
            float2 p0 = *(const float2*)&pl[(r0 + gq)     * RS + k0];
            float2 p1 = *(const float2*)&pl[(r0 + gq + 8) * RS + k0];
            float2 p2 = *(const float2*)&pl[(r0 + gq)     * RS + k0 + 8];
            float2 p3 = *(const float2*)&pl[(r0 + gq + 8) * RS + k0 + 8];
            a[mt][0] = f22h(p0.x, p0.y);
            a[mt][1] = f22h(p1.x, p1.y);
            a[mt][2] = f22h(p2.x, p2.y);
            a[mt][3] = f22h(p3.x, p3.y);
        }
        #pragma unroll
        for (int nt = 0; nt < 4; nt++) {
            const int ch = h32 + nt * 8 + gq;
            uint32_t b0 = *(const uint32_t*)&vt[(long)ch * 64 + k0];
            uint32_t b1 = *(const uint32_t*)&vt[(long)ch * 64 + k0 + 8];
            #pragma unroll
            for (int mt = 0; mt < 2; mt++)
                mma_f16(acc2[mt][nt], a[mt][0], a[mt][1], a[mt][2], a[mt][3], b0, b1);
        }
    }

    #pragma unroll
    for (int mt = 0; mt < 2; mt++) {
        #pragma unroll
        for (int nt = 0; nt < 4; nt++) {
            const int col = h32 + nt * 8 + 2 * tg;
            const long r1 = rowbase + qb + mt * 16 + gq;
            *(__half2*)&g_qk[r1 * 512 + col] =
                __floats2half2_rn(acc2[mt][nt][0], acc2[mt][nt][1]);
            *(__half2*)&g_qk[(r1 + 8) * 512 + col] =
                __floats2half2_rn(acc2[mt][nt][2], acc2[mt][nt][3]);
        }
    }
}

// ---------------------------------------------------------------------------
// Kernel C: proj, fp16 m16n8k16, A and B via ldmatrix.x4 (R16 verbatim).
// ---------------------------------------------------------------------------
#define PRS 40
#define P_TBYTES (128 * PRS * 2)
#define P_BUF (2 * P_TBYTES)
#define SMEM_PROJ (2 * P_BUF)

__global__ __launch_bounds__(256) void proj_mma(
    const float* __restrict__ b_proj, float* __restrict__ out)
{
    extern __shared__ char smc[];
    const int tid = threadIdx.x;
    const long row0 = (long)blockIdx.y * 128;
    const int colb = blockIdx.x * 128;

    const int ldr = tid >> 2, hoff = (tid & 3) << 3;
    int srcrow[2];
    {
        long rows[2] = { row0 + ldr, row0 + ldr + 64 };
        #pragma unroll
        for (int u = 0; u < 2; u++) {
            int b = (int)(rows[u] >> 14);
            int n = (int)(rows[u] & 16383);
            int i = n >> 7, j = n & 127;
            srcrow[u] = ((b << 8) + (i >> 3) * 16 + (j >> 3)) * 64 + (i & 7) * 8 + (j & 7);
        }
    }
    const __half* a_src[2] = {
        g_qk + (long)srcrow[0] * 512 + hoff,
        g_qk + (long)srcrow[1] * 512 + hoff
    };
    const __half* b_src[2] = {
        g_w16p + (long)(colb + ldr) * 256 + hoff,
        g_w16p + (long)(colb + ldr + 64) * 256 + hoff
    };

    uint32_t smem_base = (uint32_t)__cvta_generic_to_shared(smc);
    uint32_t a_dst[2] = {
        smem_base + (uint32_t)(ldr * PRS + hoff) * 2,
        smem_base + (uint32_t)((ldr + 64) * PRS + hoff) * 2
    };
    uint32_t b_dst[2] = {
        smem_base + P_TBYTES + (uint32_t)(ldr * PRS + hoff) * 2,
        smem_base + P_TBYTES + (uint32_t)((ldr + 64) * PRS + hoff) * 2
    };

    const int lane = tid & 31, w = tid >> 5;
    const int wm = (w >> 1) * 32;
    const int wn = (w & 1) * 64;
    const int gq = lane >> 2, tg = lane & 3;

    const uint32_t alm = (uint32_t)(((((lane & 7) + (((lane >> 3) & 1) << 3)) * PRS)
                                     + ((lane >> 4) << 3)) * 2);
    const uint32_t blm = (uint32_t)(((((lane & 7) + ((lane >> 4) << 3)) * PRS)
                                     + (((lane >> 3) & 1) << 3)) * 2);

    float acc[2][8][4];
    #pragma unroll
    for (int mt = 0; mt < 2; mt++)
        #pragma unroll
        for (int nt = 0; nt < 8; nt++)
            #pragma unroll
            for (int q = 0; q < 4; q++) acc[mt][nt][q] = 0.f;

    {
        #pragma unroll
        for (int u = 0; u < 2; u++) { CPA16(a_dst[u], a_src[u]); CPA16(b_dst[u], b_src[u]); }
        CP_COMMIT();
    }

    for (int kb = 0; kb < 8; ++kb) {
        CP_WAIT0();
        __syncthreads();
        if (kb < 7) {
            uint32_t off = (uint32_t)(((kb + 1) & 1) * P_BUF);
            #pragma unroll
            for (int u = 0; u < 2; u++) {
                CPA16(a_dst[u] + off, a_src[u] + (kb + 1) * 32);
                CPA16(b_dst[u] + off, b_src[u] + (kb + 1) * 32);
            }
            CP_COMMIT();
        }
        const uint32_t sA_u = smem_base + (uint32_t)((kb & 1) * P_BUF) + alm;
        const uint32_t sB_u = smem_base + (uint32_t)((kb & 1) * P_BUF) + P_TBYTES + blm;

        #pragma unroll
        for (int ks = 0; ks < 2; ++ks) {
            uint32_t af[2][4];
            #pragma unroll
            for (int mt = 0; mt < 2; mt++)
                LDMX4(af[mt][0], af[mt][1], af[mt][2], af[mt][3],
                      sA_u + (uint32_t)((((wm + mt * 16) * PRS) + ks * 16) * 2));
            uint32_t br[16];
            #pragma unroll
            for (int np = 0; np < 4; np++)
                LDMX4(br[4 * np], br[4 * np + 1], br[4 * np + 2], br[4 * np + 3],
                      sB_u + (uint32_t)((((wn + np * 16) * PRS) + ks * 16) * 2));
            #pragma unroll
            for (int nt = 0; nt < 8; nt++) {
                uint32_t b0 = br[2 * nt], b1 = br[2 * nt + 1];
                mma_f16(acc[0][nt], af[0][0], af[0][1], af[0][2], af[0][3], b0, b1);
                mma_f16(acc[1][nt], af[1][0], af[1][1], af[1][2], af[1][3], b0, b1);
            }
        }
    }

    #pragma unroll
    for (int mt = 0; mt < 2; mt++) {
        #pragma unroll
        for (int nt = 0; nt < 8; nt++) {
            const int col = colb + wn + nt * 8 + tg * 2;
            const float2 bv = *(const float2*)(b_proj + col);
            const long r1 = row0 + wm + mt * 16 + gq;
            *(float2*)(out + r1 * NC + col) =
                make_float2(acc[mt][nt][0] + bv.x, acc[mt][nt][1] + bv.y);
            *(float2*)(out + (r1 + 8) * NC + col) =
                make_float2(acc[mt][nt][2] + bv.x, acc[mt][nt][3] + bv.y);
        }
    }
}

// ---------------------------------------------------------------------------
extern "C" void kernel_launch(void* const* d_in, const int* in_sizes, int n_in,
                              void* d_out, int out_size)
{
    const float* x      = (const float*)d_in[0];
    const float* query  = (const float*)d_in[1];
    const float* W_qk   = (const float*)d_in[2];
    const float* W_v    = (const float*)d_in[3];
    const float* W_proj = (const float*)d_in[4];
    const float* b_proj = (const float*)d_in[5];
    const float* W_pre  = (const float*)d_in[6];
    const float* W_post = (const float*)d_in[7];
    float* out = (float*)d_out;

    cudaFuncSetAttribute(qkv_mma, cudaFuncAttributeMaxDynamicSharedMemorySize, SMEM_QKV);
    cudaFuncSetAttribute(attn_kernel, cudaFuncAttributeMaxDynamicSharedMemorySize, SMEM_ATTN_BYTES);
    cudaFuncSetAttribute(proj_mma, cudaFuncAttributeMaxDynamicSharedMemorySize, SMEM_PROJ);

    cvt_weights<<<128, 256>>>(W_qk, W_v, W_proj);
    qkv_mma<<<dim3(12, 1024), 256, SMEM_QKV>>>(x, query);
    attn_kernel<<<NWIN * 2, 256, SMEM_ATTN_BYTES>>>(W_pre, W_post);
    proj_mma<<<dim3(2, 1024), 256, SMEM_PROJ>>>(b_proj, out);
}